// round 5
// baseline (speedup 1.0000x reference)
#include <cuda_runtime.h>
#include <cstdint>

#define M_TILE   64
#define H        256
#define H3       768
#define LATENT   128
#define T_STEPS  180
#define HPAD     260          // h row pitch in floats (16B-aligned, conflict-benign)
#define NCTA     128
#define NTHR     256
#define OFFJ     (16*H)       // float offset between a thread's consecutive W rows

// packed fp32x2 FMA (sm_103a FFMA2)
#define FMA2(acc, a, b) asm("fma.rn.f32x2 %0, %1, %2, %0;" : "+l"(acc) : "l"(a), "l"(b))

__device__ __forceinline__ float lo32(unsigned long long v){ return __uint_as_float((unsigned)(v & 0xffffffffull)); }
__device__ __forceinline__ float hi32(unsigned long long v){ return __uint_as_float((unsigned)(v >> 32)); }
__device__ __forceinline__ ulonglong2 ld2(const float* p){ return *reinterpret_cast<const ulonglong2*>(p); }

__device__ __forceinline__ float sigmoidf_(float x){ return 1.0f/(1.0f + __expf(-x)); }
__device__ __forceinline__ float tanhf_(float x){ return 2.0f/(1.0f + __expf(-2.0f*x)) - 1.0f; }

__global__ __launch_bounds__(NTHR, 1)
void gru_decoder_kernel(const float* __restrict__ z,
                        const float* __restrict__ fc_w,
                        const float* __restrict__ fc_b,
                        const float* __restrict__ b_ih,
                        const float* __restrict__ w_hh,
                        const float* __restrict__ b_hh,
                        const float* __restrict__ out_w,
                        const float* __restrict__ out_b,
                        float* __restrict__ out)
{
    extern __shared__ float smem[];
    float* hbufA = smem;                    // [64][HPAD]
    float* hbufB = smem + M_TILE*HPAD;      // [64][HPAD]
    float* bsr   = smem + 2*M_TILE*HPAD;    // [256] b_ih_r + b_hh_r
    float* bsz   = bsr + H;                 // [256] b_ih_z + b_hh_z
    float* bin   = bsz + H;                 // [256] b_ih_n
    float* bhn   = bin + H;                 // [256] b_hh_n
    float* ows   = bhn + H;                 // [2][256]
    float* obs   = ows + 2*H;               // [2]

    const int tid = threadIdx.x;
    const int mg  = tid & 15;               // 16 m-groups, rows mg + 16*mm
    const int jg  = tid >> 4;               // 16 j-groups, cols jb*64 + jg + 16*jj
    const int mbase = blockIdx.x * M_TILE;

    // ---- preload biases / output weights into smem ----
    for (int i = tid; i < H; i += NTHR) {
        bsr[i] = b_ih[i]       + b_hh[i];
        bsz[i] = b_ih[H + i]   + b_hh[H + i];
        bin[i] = b_ih[2*H + i];
        bhn[i] = b_hh[2*H + i];
        ows[i]     = out_w[i];
        ows[H + i] = out_w[H + i];
    }
    if (tid < 2) obs[tid] = out_b[tid];

    // ---- stage z tile into hbufB (coalesced) ----
    for (int i = tid; i < M_TILE * (LATENT/4); i += NTHR) {
        int m  = i / (LATENT/4);
        int k4 = i % (LATENT/4);
        reinterpret_cast<float4*>(hbufB + m*HPAD)[k4] =
            reinterpret_cast<const float4*>(z + (size_t)(mbase+m)*LATENT)[k4];
    }
    __syncthreads();

    // ---- h0 = tanh(z @ fc_w^T + fc_b) into hbufA ----
    for (int jb = 0; jb < 4; jb++) {
        float acc[4][4];
        #pragma unroll
        for (int a=0;a<4;a++) { acc[a][0]=0.f; acc[a][1]=0.f; acc[a][2]=0.f; acc[a][3]=0.f; }
        const float* wb = fc_w + (size_t)(jb*64 + jg) * LATENT;
        for (int k4 = 0; k4 < LATENT/4; k4++) {
            float4 zv[4], wv[4];
            #pragma unroll
            for (int mm=0;mm<4;mm++)
                zv[mm] = *reinterpret_cast<const float4*>(hbufB + (mg+16*mm)*HPAD + 4*k4);
            #pragma unroll
            for (int jj=0;jj<4;jj++)
                wv[jj] = *reinterpret_cast<const float4*>(wb + jj*(16*LATENT) + 4*k4);
            #pragma unroll
            for (int mm=0;mm<4;mm++)
                #pragma unroll
                for (int jj=0;jj<4;jj++)
                    acc[mm][jj] += zv[mm].x*wv[jj].x + zv[mm].y*wv[jj].y
                                 + zv[mm].z*wv[jj].z + zv[mm].w*wv[jj].w;
        }
        #pragma unroll
        for (int jj=0;jj<4;jj++) {
            int j = jb*64 + jg + 16*jj;
            float fb = fc_b[j];
            #pragma unroll
            for (int mm=0;mm<4;mm++)
                hbufA[(mg+16*mm)*HPAD + j] = tanhf_(acc[mm][jj] + fb);
        }
    }
    __syncthreads();

    float* hc = hbufA;   // current h
    float* hn = hbufB;   // next h

    for (int t = 0; t < T_STEPS; t++) {
        for (int jb = 0; jb < 4; jb++) {
            const int j0 = jb*64 + jg;
            const float* wr_base = w_hh + (size_t)j0 * H;              // r-gate rows
            const float* wz_base = wr_base + (size_t)H * H;            // z-gate rows
            const float* hrow    = hc + mg*HPAD;

            // ================= phase A: r and z gates =================
            unsigned long long ar[4][4], az[4][4];
            #pragma unroll
            for (int mm=0;mm<4;mm++)
                #pragma unroll
                for (int jj=0;jj<4;jj++) { ar[mm][jj]=0ull; az[mm][jj]=0ull; }

            ulonglong2 wr0[4], wr1[4], wz0[4], wz1[4];
            #pragma unroll
            for (int jj=0;jj<4;jj++) {
                wr0[jj] = ld2(wr_base + jj*OFFJ);
                wz0[jj] = ld2(wz_base + jj*OFFJ);
            }
            for (int k4 = 0; k4 < 64; k4 += 2) {
                // ---- half 1: compute k4 from buf0, prefetch k4+1 into buf1 ----
                #pragma unroll
                for (int jj=0;jj<4;jj++) {
                    wr1[jj] = ld2(wr_base + jj*OFFJ + 4*(k4+1));
                    wz1[jj] = ld2(wz_base + jj*OFFJ + 4*(k4+1));
                }
                {
                    ulonglong2 hv[4];
                    #pragma unroll
                    for (int mm=0;mm<4;mm++) hv[mm] = ld2(hrow + mm*(16*HPAD) + 4*k4);
                    #pragma unroll
                    for (int mm=0;mm<4;mm++)
                        #pragma unroll
                        for (int jj=0;jj<4;jj++) {
                            FMA2(ar[mm][jj], hv[mm].x, wr0[jj].x);
                            FMA2(ar[mm][jj], hv[mm].y, wr0[jj].y);
                            FMA2(az[mm][jj], hv[mm].x, wz0[jj].x);
                            FMA2(az[mm][jj], hv[mm].y, wz0[jj].y);
                        }
                }
                // ---- half 2: compute k4+1 from buf1, prefetch k4+2 into buf0 ----
                int k2 = (k4+2 < 64) ? (k4+2) : 63;
                #pragma unroll
                for (int jj=0;jj<4;jj++) {
                    wr0[jj] = ld2(wr_base + jj*OFFJ + 4*k2);
                    wz0[jj] = ld2(wz_base + jj*OFFJ + 4*k2);
                }
                {
                    ulonglong2 hv[4];
                    #pragma unroll
                    for (int mm=0;mm<4;mm++) hv[mm] = ld2(hrow + mm*(16*HPAD) + 4*(k4+1));
                    #pragma unroll
                    for (int mm=0;mm<4;mm++)
                        #pragma unroll
                        for (int jj=0;jj<4;jj++) {
                            FMA2(ar[mm][jj], hv[mm].x, wr1[jj].x);
                            FMA2(ar[mm][jj], hv[mm].y, wr1[jj].y);
                            FMA2(az[mm][jj], hv[mm].x, wz1[jj].x);
                            FMA2(az[mm][jj], hv[mm].y, wz1[jj].y);
                        }
                }
            }

            // ---- gates r, z ----
            float r_[4][4], zg_[4][4];
            #pragma unroll
            for (int jj=0;jj<4;jj++) {
                int j = j0 + 16*jj;
                float br = bsr[j], bz = bsz[j];
                #pragma unroll
                for (int mm=0;mm<4;mm++) {
                    r_[mm][jj]  = sigmoidf_(lo32(ar[mm][jj]) + hi32(ar[mm][jj]) + br);
                    zg_[mm][jj] = sigmoidf_(lo32(az[mm][jj]) + hi32(az[mm][jj]) + bz);
                }
            }

            // ================= phase B: n gate =================
            const float* wn_base = w_hh + (size_t)(2*H + j0) * H;
            unsigned long long an[4][4];
            #pragma unroll
            for (int mm=0;mm<4;mm++)
                #pragma unroll
                for (int jj=0;jj<4;jj++) an[mm][jj]=0ull;

            ulonglong2 wn0[4], wn1[4];
            #pragma unroll
            for (int jj=0;jj<4;jj++) wn0[jj] = ld2(wn_base + jj*OFFJ);

            for (int k4 = 0; k4 < 64; k4 += 2) {
                #pragma unroll
                for (int jj=0;jj<4;jj++) wn1[jj] = ld2(wn_base + jj*OFFJ + 4*(k4+1));
                {
                    ulonglong2 hv[4];
                    #pragma unroll
                    for (int mm=0;mm<4;mm++) hv[mm] = ld2(hrow + mm*(16*HPAD) + 4*k4);
                    #pragma unroll
                    for (int mm=0;mm<4;mm++)
                        #pragma unroll
                        for (int jj=0;jj<4;jj++) {
                            FMA2(an[mm][jj], hv[mm].x, wn0[jj].x);
                            FMA2(an[mm][jj], hv[mm].y, wn0[jj].y);
                        }
                }
                int k2 = (k4+2 < 64) ? (k4+2) : 63;
                #pragma unroll
                for (int jj=0;jj<4;jj++) wn0[jj] = ld2(wn_base + jj*OFFJ + 4*k2);
                {
                    ulonglong2 hv[4];
                    #pragma unroll
                    for (int mm=0;mm<4;mm++) hv[mm] = ld2(hrow + mm*(16*HPAD) + 4*(k4+1));
                    #pragma unroll
                    for (int mm=0;mm<4;mm++)
                        #pragma unroll
                        for (int jj=0;jj<4;jj++) {
                            FMA2(an[mm][jj], hv[mm].x, wn1[jj].x);
                            FMA2(an[mm][jj], hv[mm].y, wn1[jj].y);
                        }
                }
            }

            // ---- n gate + h update (write to hn) ----
            #pragma unroll
            for (int jj=0;jj<4;jj++) {
                int j = j0 + 16*jj;
                float bi = bin[j], bh = bhn[j];
                #pragma unroll
                for (int mm=0;mm<4;mm++) {
                    float ghn = lo32(an[mm][jj]) + hi32(an[mm][jj]);
                    float nv  = tanhf_(bi + r_[mm][jj] * (ghn + bh));
                    float hold = hc[(mg+16*mm)*HPAD + j];
                    hn[(mg+16*mm)*HPAD + j] = nv + zg_[mm][jj] * (hold - nv);
                }
            }
        } // jb

        __syncthreads();

        // ---- fused output projection: out[b,t,:] = h_new @ out_w^T + out_b ----
        if (tid < 128) {
            int m = tid >> 1, o = tid & 1;
            float s0 = obs[o], s1 = 0.f;
            const float4* hp = reinterpret_cast<const float4*>(hn + m*HPAD);
            const float4* wp = reinterpret_cast<const float4*>(ows + o*H);
            #pragma unroll 8
            for (int k4 = 0; k4 < 64; k4 += 2) {
                float4 a0 = hp[k4],   b0 = wp[k4];
                float4 a1 = hp[k4+1], b1 = wp[k4+1];
                s0 += a0.x*b0.x + a0.y*b0.y + a0.z*b0.z + a0.w*b0.w;
                s1 += a1.x*b1.x + a1.y*b1.y + a1.z*b1.z + a1.w*b1.w;
            }
            out[((size_t)(mbase+m)*T_STEPS + t)*2 + o] = s0 + s1;
        }

        // swap buffers (no extra sync needed: per-thread program order +
        // the single barrier above covers all cross-buffer hazards)
        float* tmp = hc; hc = hn; hn = tmp;
    }
}

extern "C" void kernel_launch(void* const* d_in, const int* in_sizes, int n_in,
                              void* d_out, int out_size)
{
    (void)in_sizes; (void)n_in; (void)out_size;
    const float* z     = (const float*)d_in[0];
    const float* fc_w  = (const float*)d_in[1];
    const float* fc_b  = (const float*)d_in[2];
    /* d_in[3] = w_ih: unused — GRU input is all-zeros, gi reduces to b_ih */
    const float* b_ih  = (const float*)d_in[4];
    const float* w_hh  = (const float*)d_in[5];
    const float* b_hh  = (const float*)d_in[6];
    const float* out_w = (const float*)d_in[7];
    const float* out_b = (const float*)d_in[8];

    const size_t smem_bytes =
        (2*M_TILE*HPAD + 4*H + 2*H + 2) * sizeof(float);   // ~139.3 KB

    cudaFuncSetAttribute(gru_decoder_kernel,
                         cudaFuncAttributeMaxDynamicSharedMemorySize,
                         (int)smem_bytes);

    gru_decoder_kernel<<<NCTA, NTHR, smem_bytes>>>(
        z, fc_w, fc_b, b_ih, w_hh, b_hh, out_w, out_b, (float*)d_out);
}

// round 7
// speedup vs baseline: 2.9781x; 2.9781x over previous
#include <cuda_runtime.h>
#include <cuda_bf16.h>
#include <cstdint>

#define T_STEPS  180
#define NCTA     128
#define NTHR     256
#define HP       264                 // padded bf16 elems per h row
#define HROW     (HP*2)              // 528 bytes per h row
#define HBUF     (64*HROW)           // 33792 B  (one bf16 plane, 64 rows)
#define BUFSTRIDE (2*HBUF)           // hi+lo planes = 67584 B

#define OFF_HA   0
#define OFF_HB   BUFSTRIDE
#define OFF_BSR  (2*BUFSTRIDE)       // 135168
#define OFF_BSZ  (OFF_BSR+1024)
#define OFF_BIN  (OFF_BSZ+1024)
#define OFF_BHN  (OFF_BIN+1024)
#define OFF_OW   (OFF_BHN+1024)
#define OFF_OB   (OFF_OW+2048)
#define OFF_OUT  (OFF_OB+16)         // 64*20*2 f32 = 10240
#define SMEM_SZ  (OFF_OUT+10240)     // 151568 B

// W in HMMA A-fragment order: [g(16)][ks(16)][mt(3)][lane(32)] uint4
__device__ __align__(16) uint4 g_wah[16*16*3*32];
__device__ __align__(16) uint4 g_wal[16*16*3*32];

__device__ __forceinline__ uint32_t smem_u32(const void* p) {
    uint32_t a;
    asm("{ .reg .u64 t; cvta.to.shared.u64 t, %1; cvt.u32.u64 %0, t; }" : "=r"(a) : "l"(p));
    return a;
}
__device__ __forceinline__ void ldsm4(uint32_t* r, uint32_t addr) {
    asm volatile("ldmatrix.sync.aligned.m8n8.x4.shared.b16 {%0,%1,%2,%3}, [%4];"
        : "=r"(r[0]), "=r"(r[1]), "=r"(r[2]), "=r"(r[3]) : "r"(addr));
}
__device__ __forceinline__ void mma_bf16(float& d0, float& d1, float& d2, float& d3,
                                         uint32_t a0, uint32_t a1, uint32_t a2, uint32_t a3,
                                         uint32_t b0, uint32_t b1) {
    asm volatile("mma.sync.aligned.m16n8k16.row.col.f32.bf16.bf16.f32 "
        "{%0,%1,%2,%3},{%4,%5,%6,%7},{%8,%9},{%0,%1,%2,%3};"
        : "+f"(d0), "+f"(d1), "+f"(d2), "+f"(d3)
        : "r"(a0), "r"(a1), "r"(a2), "r"(a3), "r"(b0), "r"(b1));
}
__device__ __forceinline__ float sigmoidf_(float x){ return 1.0f/(1.0f + __expf(-x)); }
__device__ __forceinline__ float tanhf_(float x){ return 2.0f/(1.0f + __expf(-2.0f*x)) - 1.0f; }
__device__ __forceinline__ float bflo(uint32_t u){ return __uint_as_float(u << 16); }
__device__ __forceinline__ float bfhi(uint32_t u){ return __uint_as_float(u & 0xffff0000u); }

// ---------- prep: w_hh [768][256] fp32 -> bf16 hi/lo in A-fragment order ----------
// row order per group g: rows (mt*256 + g*16 + rowlocal): mt 0=r,1=z,2=n gates
__global__ void prep_w(const float* __restrict__ w) {
    int idx = blockIdx.x * 256 + threadIdx.x;         // 96*256 = 24576
    int l  = idx & 31;
    int r1 = idx >> 5;
    int mt = r1 % 3;  r1 /= 3;
    int ks = r1 & 15; int g = r1 >> 4;
    int gr = l >> 2, tig = l & 3;
    uint32_t hreg[4], lreg[4];
    #pragma unroll
    for (int rg = 0; rg < 4; rg++) {
        uint32_t hv = 0, lv = 0;
        #pragma unroll
        for (int hh = 0; hh < 2; hh++) {
            int i   = rg*2 + hh;
            int row = gr + 8*((i >> 1) & 1);
            int col = 2*tig + (i & 1) + 8*(i >> 2);
            float x = w[(mt*256 + g*16 + row)*256 + ks*16 + col];
            __nv_bfloat16 bh = __float2bfloat16(x);
            __nv_bfloat16 bl = __float2bfloat16(x - __bfloat162float(bh));
            hv |= (uint32_t)__bfloat16_as_ushort(bh) << (16*hh);
            lv |= (uint32_t)__bfloat16_as_ushort(bl) << (16*hh);
        }
        hreg[rg] = hv; lreg[rg] = lv;
    }
    g_wah[idx] = make_uint4(hreg[0], hreg[1], hreg[2], hreg[3]);
    g_wal[idx] = make_uint4(lreg[0], lreg[1], lreg[2], lreg[3]);
}

__global__ __launch_bounds__(NTHR, 1)
void gru_hmma_kernel(const float* __restrict__ z,
                     const float* __restrict__ fc_w,
                     const float* __restrict__ fc_b,
                     const float* __restrict__ b_ih,
                     const float* __restrict__ b_hh,
                     const float* __restrict__ out_w,
                     const float* __restrict__ out_b,
                     float* __restrict__ out)
{
    extern __shared__ char sm[];
    const uint32_t sbase = smem_u32(sm);
    const int tid = threadIdx.x;
    const int w   = tid >> 5;
    const int l   = tid & 31;
    const int gr  = l >> 2, tig = l & 3;
    const int mbase = blockIdx.x * 64;

    float* bsr = (float*)(sm + OFF_BSR);
    float* bsz = (float*)(sm + OFF_BSZ);
    float* bin = (float*)(sm + OFF_BIN);
    float* bhn = (float*)(sm + OFF_BHN);
    float* ow  = (float*)(sm + OFF_OW);
    float* ob  = (float*)(sm + OFF_OB);
    float* obuf= (float*)(sm + OFF_OUT);

    // biases / output weights
    {
        int i = tid;
        bsr[i] = b_ih[i]       + b_hh[i];
        bsz[i] = b_ih[256 + i] + b_hh[256 + i];
        bin[i] = b_ih[512 + i];
        bhn[i] = b_hh[512 + i];
        ow[i]       = out_w[i];
        ow[256 + i] = out_w[256 + i];
        if (i < 2) ob[i] = out_b[i];
    }

    // ---- stage z [64][128] f32 into HB region, compute h0 into HA ----
    {
        float* zs = (float*)(sm + OFF_HB);
        const float4* zp = (const float4*)(z + (size_t)mbase * 128);
        for (int i = tid; i < 2048; i += NTHR) ((float4*)zs)[i] = zp[i];
        __syncthreads();

        const int j = tid;
        float acc[64];
        #pragma unroll
        for (int m = 0; m < 64; m++) acc[m] = 0.f;
        const float* wr = fc_w + (size_t)j * 128;
        for (int k8 = 0; k8 < 16; k8++) {
            float4 wa = *(const float4*)(wr + k8*8);
            float4 wb = *(const float4*)(wr + k8*8 + 4);
            #pragma unroll
            for (int m = 0; m < 64; m++) {
                const float* zr = zs + m*128 + k8*8;
                float4 za = *(const float4*)zr;
                float4 zc = *(const float4*)(zr + 4);
                acc[m] += za.x*wa.x + za.y*wa.y + za.z*wa.z + za.w*wa.w
                        + zc.x*wb.x + zc.y*wb.y + zc.z*wb.z + zc.w*wb.w;
            }
        }
        float fb = fc_b[j];
        unsigned short* HHI = (unsigned short*)(sm + OFF_HA);
        unsigned short* HLO = (unsigned short*)(sm + OFF_HA + HBUF);
        for (int m = 0; m < 64; m++) {
            float h = tanhf_(acc[m] + fb);
            __nv_bfloat16 hb = __float2bfloat16(h);
            __nv_bfloat16 lb = __float2bfloat16(h - __bfloat162float(hb));
            HHI[m*HP + j] = __bfloat16_as_ushort(hb);
            HLO[m*HP + j] = __bfloat16_as_ushort(lb);
        }
        __syncthreads();
    }

    // per-lane ldmatrix row offset: lanes 0-7 m0, 8-15 m1, 16-23 m2, 24-31 m3
    const uint32_t rowoff = (uint32_t)(((l & 7) + 8*((l >> 4) & 1)) * HROW + ((l >> 3) & 1) * 16);

    uint32_t cur = OFF_HA, nxt = OFF_HB;

    for (int t = 0; t < T_STEPS; t++) {
        const uint32_t curb = sbase + cur;

        #pragma unroll 1
        for (int gi = 0; gi < 2; gi++) {
            const int g = w + 8*gi;

            float acc[3][8][4];
            #pragma unroll
            for (int mt = 0; mt < 3; mt++)
                #pragma unroll
                for (int nt = 0; nt < 8; nt++)
                    #pragma unroll
                    for (int r = 0; r < 4; r++) acc[mt][nt][r] = 0.f;

            const uint4* pH = g_wah + (size_t)(g*16)*96 + l;
            const uint4* pL = g_wal + (size_t)(g*16)*96 + l;
            uint4 ah[3], al[3], ahn[3], aln[3];
            ah[0] = pH[0];  ah[1] = pH[32];  ah[2] = pH[64];
            al[0] = pL[0];  al[1] = pL[32];  al[2] = pL[64];

            #pragma unroll 2
            for (int ks = 0; ks < 16; ks++) {
                if (ks < 15) {
                    const uint4* qH = pH + (ks+1)*96;
                    const uint4* qL = pL + (ks+1)*96;
                    ahn[0] = qH[0]; ahn[1] = qH[32]; ahn[2] = qH[64];
                    aln[0] = qL[0]; aln[1] = qL[32]; aln[2] = qL[64];
                }
                // B fragments: h hi/lo for 8 n-tiles (64 batch) at this k-step
                uint32_t bfh[16], bfl[16];
                #pragma unroll
                for (int np = 0; np < 4; np++) {
                    uint32_t r4[4];
                    uint32_t a = curb + (uint32_t)(np*(16*HROW) + ks*32) + rowoff;
                    ldsm4(r4, a);
                    bfh[4*np+0] = r4[0]; bfh[4*np+1] = r4[1];
                    bfh[4*np+2] = r4[2]; bfh[4*np+3] = r4[3];
                    ldsm4(r4, a + HBUF);
                    bfl[4*np+0] = r4[0]; bfl[4*np+1] = r4[1];
                    bfl[4*np+2] = r4[2]; bfl[4*np+3] = r4[3];
                }
                // product 0: Whi * h_hi
                #pragma unroll
                for (int mt = 0; mt < 3; mt++)
                    #pragma unroll
                    for (int nt = 0; nt < 8; nt++)
                        mma_bf16(acc[mt][nt][0], acc[mt][nt][1], acc[mt][nt][2], acc[mt][nt][3],
                                 ah[mt].x, ah[mt].y, ah[mt].z, ah[mt].w, bfh[2*nt], bfh[2*nt+1]);
                // product 1: Whi * h_lo
                #pragma unroll
                for (int mt = 0; mt < 3; mt++)
                    #pragma unroll
                    for (int nt = 0; nt < 8; nt++)
                        mma_bf16(acc[mt][nt][0], acc[mt][nt][1], acc[mt][nt][2], acc[mt][nt][3],
                                 ah[mt].x, ah[mt].y, ah[mt].z, ah[mt].w, bfl[2*nt], bfl[2*nt+1]);
                // product 2: Wlo * h_hi
                #pragma unroll
                for (int mt = 0; mt < 3; mt++)
                    #pragma unroll
                    for (int nt = 0; nt < 8; nt++)
                        mma_bf16(acc[mt][nt][0], acc[mt][nt][1], acc[mt][nt][2], acc[mt][nt][3],
                                 al[mt].x, al[mt].y, al[mt].z, al[mt].w, bfh[2*nt], bfh[2*nt+1]);
                #pragma unroll
                for (int q = 0; q < 3; q++) { ah[q] = ahn[q]; al[q] = aln[q]; }
            }

            // ---- epilogue: gates + h update, all in registers ----
            const unsigned short* CHI = (const unsigned short*)(sm + cur);
            const unsigned short* CLO = CHI + HBUF/2;
            unsigned short* NHI = (unsigned short*)(sm + nxt);
            unsigned short* NLO = NHI + HBUF/2;
            const int jA = 16*g + gr;
            const float brA = bsr[jA], bzA = bsz[jA], biA = bin[jA], bhA = bhn[jA];
            const float brB = bsr[jA+8], bzB = bsz[jA+8], biB = bin[jA+8], bhB = bhn[jA+8];
            #pragma unroll
            for (int r = 0; r < 4; r++) {
                const int j  = jA + 8*(r >> 1);
                const float br = (r >> 1) ? brB : brA;
                const float bz = (r >> 1) ? bzB : bzA;
                const float bi = (r >> 1) ? biB : biA;
                const float bh = (r >> 1) ? bhB : bhA;
                #pragma unroll
                for (int nt = 0; nt < 8; nt++) {
                    const int b = nt*8 + 2*tig + (r & 1);
                    float hold = bflo((uint32_t)CHI[b*HP + j]) + bflo((uint32_t)CLO[b*HP + j]);
                    float rr = sigmoidf_(acc[0][nt][r] + br);
                    float zz = sigmoidf_(acc[1][nt][r] + bz);
                    float nn = tanhf_(bi + rr * (acc[2][nt][r] + bh));
                    float hnew = nn + zz * (hold - nn);
                    __nv_bfloat16 hb = __float2bfloat16(hnew);
                    __nv_bfloat16 lb = __float2bfloat16(hnew - __bfloat162float(hb));
                    NHI[b*HP + j] = __bfloat16_as_ushort(hb);
                    NLO[b*HP + j] = __bfloat16_as_ushort(lb);
                }
            }
        }

        __syncthreads();   // h_next complete, visible to all

        // ---- output projection into SMEM ring: out[b,t,:] = h_new @ ow^T + ob ----
        if (tid < 128) {
            const int m = tid >> 1, o = tid & 1;
            float s = ob[o];
            const uint4* hh = (const uint4*)(sm + nxt + (size_t)m*HROW);
            const uint4* hl = (const uint4*)(sm + nxt + HBUF + (size_t)m*HROW);
            const float* wp = ow + o*256;
            #pragma unroll 8
            for (int i = 0; i < 32; i++) {
                uint4 Hv = hh[i], Lv = hl[i];
                const uint32_t hw[4] = {Hv.x, Hv.y, Hv.z, Hv.w};
                const uint32_t lw[4] = {Lv.x, Lv.y, Lv.z, Lv.w};
                const float* wq = wp + i*8;
                #pragma unroll
                for (int q = 0; q < 4; q++) {
                    float e0 = bflo(hw[q]) + bflo(lw[q]);
                    float e1 = bfhi(hw[q]) + bfhi(lw[q]);
                    s += e0 * wq[2*q] + e1 * wq[2*q + 1];
                }
            }
            obuf[(m*20 + (t % 20))*2 + o] = s;
        }

        // ---- coalesced flush every 20 steps (180 = 9*20) ----
        if ((t % 20) == 19) {
            __syncthreads();
            const int m = tid >> 2, q = tid & 3;
            float* dst = out + (size_t)(mbase + m)*360 + (t - 19)*2 + q*10;
            const float* src = obuf + m*40 + q*10;
            #pragma unroll
            for (int i = 0; i < 10; i++) dst[i] = src[i];
        }

        uint32_t tmp = cur; cur = nxt; nxt = tmp;
    }
}

extern "C" void kernel_launch(void* const* d_in, const int* in_sizes, int n_in,
                              void* d_out, int out_size)
{
    (void)in_sizes; (void)n_in; (void)out_size;
    const float* z     = (const float*)d_in[0];
    const float* fc_w  = (const float*)d_in[1];
    const float* fc_b  = (const float*)d_in[2];
    /* d_in[3] = w_ih unused: GRU input is all-zeros, gi == b_ih */
    const float* b_ih  = (const float*)d_in[4];
    const float* w_hh  = (const float*)d_in[5];
    const float* b_hh  = (const float*)d_in[6];
    const float* out_w = (const float*)d_in[7];
    const float* out_b = (const float*)d_in[8];

    prep_w<<<96, 256>>>(w_hh);

    cudaFuncSetAttribute(gru_hmma_kernel,
                         cudaFuncAttributeMaxDynamicSharedMemorySize, SMEM_SZ);
    gru_hmma_kernel<<<NCTA, NTHR, SMEM_SZ>>>(
        z, fc_w, fc_b, b_ih, b_hh, out_w, out_b, (float*)d_out);
}

// round 10
// speedup vs baseline: 3.8080x; 1.2787x over previous
#include <cuda_runtime.h>
#include <cuda_fp16.h>
#include <cstdint>

// R8 = R7 resubmit (R7 bench was an infra failure: container died twice,
// kernel never measured). fp16 2-product GEMM: W = Whi + Wlo (fp16 residual),
// h stored as single fp16 plane. 12288 MMAs/CTA-step vs 18432 in R6.

#define T_STEPS  180
#define NCTA     128
#define NTHR     256
#define HP       264                 // padded fp16 elems per h row
#define HROW     (HP*2)              // 528 bytes per h row
#define HBUF     (64*HROW)           // 33792 B : one fp16 plane, 64 rows

#define OFF_HA   0
#define OFF_HB   HBUF                // 33792
#define OFF_BSR  (2*HBUF)            // 67584
#define OFF_BSZ  (OFF_BSR+1024)
#define OFF_BIN  (OFF_BSZ+1024)
#define OFF_BHN  (OFF_BIN+1024)
#define OFF_OW   (OFF_BHN+1024)      // 71680
#define OFF_OB   (OFF_OW+2048)
#define OFF_OUT  (OFF_OB+16)         // 64*20*2 f32 = 10240
#define SMEM_SZ  (OFF_OUT+10240)     // 83984 B

// W in HMMA A-fragment order: [g(16)][ks(16)][mt(3)][lane(32)] uint4
__device__ __align__(16) uint4 g_wah[16*16*3*32];   // fp16 hi plane
__device__ __align__(16) uint4 g_wal[16*16*3*32];   // fp16 lo (residual) plane

__device__ __forceinline__ uint32_t smem_u32(const void* p) {
    uint32_t a;
    asm("{ .reg .u64 t; cvta.to.shared.u64 t, %1; cvt.u32.u64 %0, t; }" : "=r"(a) : "l"(p));
    return a;
}
__device__ __forceinline__ void ldsm4(uint32_t* r, uint32_t addr) {
    asm volatile("ldmatrix.sync.aligned.m8n8.x4.shared.b16 {%0,%1,%2,%3}, [%4];"
        : "=r"(r[0]), "=r"(r[1]), "=r"(r[2]), "=r"(r[3]) : "r"(addr));
}
__device__ __forceinline__ void mma_f16(float& d0, float& d1, float& d2, float& d3,
                                        uint32_t a0, uint32_t a1, uint32_t a2, uint32_t a3,
                                        uint32_t b0, uint32_t b1) {
    asm volatile("mma.sync.aligned.m16n8k16.row.col.f32.f16.f16.f32 "
        "{%0,%1,%2,%3},{%4,%5,%6,%7},{%8,%9},{%0,%1,%2,%3};"
        : "+f"(d0), "+f"(d1), "+f"(d2), "+f"(d3)
        : "r"(a0), "r"(a1), "r"(a2), "r"(a3), "r"(b0), "r"(b1));
}
__device__ __forceinline__ float sigmoidf_(float x){ return 1.0f/(1.0f + __expf(-x)); }
__device__ __forceinline__ float tanhf_(float x){ return 2.0f/(1.0f + __expf(-2.0f*x)) - 1.0f; }

// ---------- prep: w_hh [768][256] fp32 -> fp16 hi + fp16 residual, A-fragment order ----------
__global__ void prep_w(const float* __restrict__ w) {
    int idx = blockIdx.x * 256 + threadIdx.x;         // 96*256 = 24576
    int l  = idx & 31;
    int r1 = idx >> 5;
    int mt = r1 % 3;  r1 /= 3;
    int ks = r1 & 15; int g = r1 >> 4;
    int gr = l >> 2, tig = l & 3;
    uint32_t hreg[4], lreg[4];
    #pragma unroll
    for (int rg = 0; rg < 4; rg++) {
        uint32_t hv = 0, lv = 0;
        #pragma unroll
        for (int hh = 0; hh < 2; hh++) {
            int i   = rg*2 + hh;
            int row = gr + 8*((i >> 1) & 1);
            int col = 2*tig + (i & 1) + 8*(i >> 2);
            float x = w[(mt*256 + g*16 + row)*256 + ks*16 + col];
            __half bh = __float2half_rn(x);
            __half bl = __float2half_rn(x - __half2float(bh));
            hv |= (uint32_t)__half_as_ushort(bh) << (16*hh);
            lv |= (uint32_t)__half_as_ushort(bl) << (16*hh);
        }
        hreg[rg] = hv; lreg[rg] = lv;
    }
    g_wah[idx] = make_uint4(hreg[0], hreg[1], hreg[2], hreg[3]);
    g_wal[idx] = make_uint4(lreg[0], lreg[1], lreg[2], lreg[3]);
}

__global__ __launch_bounds__(NTHR, 1)
void gru_hmma_kernel(const float* __restrict__ z,
                     const float* __restrict__ fc_w,
                     const float* __restrict__ fc_b,
                     const float* __restrict__ b_ih,
                     const float* __restrict__ b_hh,
                     const float* __restrict__ out_w,
                     const float* __restrict__ out_b,
                     float* __restrict__ out)
{
    extern __shared__ char sm[];
    const uint32_t sbase = smem_u32(sm);
    const int tid = threadIdx.x;
    const int w   = tid >> 5;
    const int l   = tid & 31;
    const int gr  = l >> 2, tig = l & 3;
    const int mbase = blockIdx.x * 64;

    float* bsr = (float*)(sm + OFF_BSR);
    float* bsz = (float*)(sm + OFF_BSZ);
    float* bin = (float*)(sm + OFF_BIN);
    float* bhn = (float*)(sm + OFF_BHN);
    float* ow  = (float*)(sm + OFF_OW);
    float* ob  = (float*)(sm + OFF_OB);
    float* obuf= (float*)(sm + OFF_OUT);

    // biases / output weights
    {
        int i = tid;
        bsr[i] = b_ih[i]       + b_hh[i];
        bsz[i] = b_ih[256 + i] + b_hh[256 + i];
        bin[i] = b_ih[512 + i];
        bhn[i] = b_hh[512 + i];
        ow[i]       = out_w[i];
        ow[256 + i] = out_w[256 + i];
        if (i < 2) ob[i] = out_b[i];
    }

    // ---- stage z [64][128] f32 into HB region, compute h0 into HA (fp16) ----
    {
        float* zs = (float*)(sm + OFF_HB);
        const float4* zp = (const float4*)(z + (size_t)mbase * 128);
        for (int i = tid; i < 2048; i += NTHR) ((float4*)zs)[i] = zp[i];
        __syncthreads();

        const int j = tid;
        float acc[64];
        #pragma unroll
        for (int m = 0; m < 64; m++) acc[m] = 0.f;
        const float* wr = fc_w + (size_t)j * 128;
        for (int k8 = 0; k8 < 16; k8++) {
            float4 wa = *(const float4*)(wr + k8*8);
            float4 wb = *(const float4*)(wr + k8*8 + 4);
            #pragma unroll
            for (int m = 0; m < 64; m++) {
                const float* zr = zs + m*128 + k8*8;
                float4 za = *(const float4*)zr;
                float4 zc = *(const float4*)(zr + 4);
                acc[m] += za.x*wa.x + za.y*wa.y + za.z*wa.z + za.w*wa.w
                        + zc.x*wb.x + zc.y*wb.y + zc.z*wb.z + zc.w*wb.w;
            }
        }
        float fb = fc_b[j];
        unsigned short* HH = (unsigned short*)(sm + OFF_HA);
        for (int m = 0; m < 64; m++) {
            float h = tanhf_(acc[m] + fb);
            HH[m*HP + j] = __half_as_ushort(__float2half_rn(h));
        }
        __syncthreads();
    }

    // per-lane ldmatrix row offset (mapping validated in R6)
    const uint32_t rowoff = (uint32_t)(((l & 7) + 8*((l >> 4) & 1)) * HROW + ((l >> 3) & 1) * 16);

    uint32_t cur = OFF_HA, nxt = OFF_HB;

    for (int t = 0; t < T_STEPS; t++) {
        const uint32_t curb = sbase + cur;

        #pragma unroll 1
        for (int gi = 0; gi < 2; gi++) {
            const int g = w + 8*gi;

            float acc[3][8][4];
            #pragma unroll
            for (int mt = 0; mt < 3; mt++)
                #pragma unroll
                for (int nt = 0; nt < 8; nt++)
                    #pragma unroll
                    for (int r = 0; r < 4; r++) acc[mt][nt][r] = 0.f;

            const uint4* pH = g_wah + (size_t)(g*16)*96 + l;
            const uint4* pL = g_wal + (size_t)(g*16)*96 + l;
            uint4 ah[3], al[3], ahn[3], aln[3];
            ah[0] = pH[0];  ah[1] = pH[32];  ah[2] = pH[64];
            al[0] = pL[0];  al[1] = pL[32];  al[2] = pL[64];

            #pragma unroll 2
            for (int ks = 0; ks < 16; ks++) {
                if (ks < 15) {
                    const uint4* qH = pH + (ks+1)*96;
                    const uint4* qL = pL + (ks+1)*96;
                    ahn[0] = qH[0]; ahn[1] = qH[32]; ahn[2] = qH[64];
                    aln[0] = qL[0]; aln[1] = qL[32]; aln[2] = qL[64];
                }
                // B fragments: h (single fp16 plane), 8 n-tiles at this k-step
                uint32_t bfh[16];
                #pragma unroll
                for (int np = 0; np < 4; np++) {
                    uint32_t r4[4];
                    ldsm4(r4, curb + (uint32_t)(np*(16*HROW) + ks*32) + rowoff);
                    bfh[4*np+0] = r4[0]; bfh[4*np+1] = r4[1];
                    bfh[4*np+2] = r4[2]; bfh[4*np+3] = r4[3];
                }
                // product 0: Whi * h
                #pragma unroll
                for (int mt = 0; mt < 3; mt++)
                    #pragma unroll
                    for (int nt = 0; nt < 8; nt++)
                        mma_f16(acc[mt][nt][0], acc[mt][nt][1], acc[mt][nt][2], acc[mt][nt][3],
                                ah[mt].x, ah[mt].y, ah[mt].z, ah[mt].w, bfh[2*nt], bfh[2*nt+1]);
                // product 1: Wlo * h
                #pragma unroll
                for (int mt = 0; mt < 3; mt++)
                    #pragma unroll
                    for (int nt = 0; nt < 8; nt++)
                        mma_f16(acc[mt][nt][0], acc[mt][nt][1], acc[mt][nt][2], acc[mt][nt][3],
                                al[mt].x, al[mt].y, al[mt].z, al[mt].w, bfh[2*nt], bfh[2*nt+1]);
                #pragma unroll
                for (int q = 0; q < 3; q++) { ah[q] = ahn[q]; al[q] = aln[q]; }
            }

            // ---- epilogue: gates + h update, all in registers ----
            const unsigned short* CH = (const unsigned short*)(sm + cur);
            unsigned short* NH = (unsigned short*)(sm + nxt);
            const int jA = 16*g + gr;
            const float brA = bsr[jA], bzA = bsz[jA], biA = bin[jA], bhA = bhn[jA];
            const float brB = bsr[jA+8], bzB = bsz[jA+8], biB = bin[jA+8], bhB = bhn[jA+8];
            #pragma unroll
            for (int r = 0; r < 4; r++) {
                const int j  = jA + 8*(r >> 1);
                const float br = (r >> 1) ? brB : brA;
                const float bz = (r >> 1) ? bzB : bzA;
                const float bi = (r >> 1) ? biB : biA;
                const float bh = (r >> 1) ? bhB : bhA;
                #pragma unroll
                for (int nt = 0; nt < 8; nt++) {
                    const int b = nt*8 + 2*tig + (r & 1);
                    float hold = __half2float(__ushort_as_half(CH[b*HP + j]));
                    float rr = sigmoidf_(acc[0][nt][r] + br);
                    float zz = sigmoidf_(acc[1][nt][r] + bz);
                    float nn = tanhf_(bi + rr * (acc[2][nt][r] + bh));
                    float hnew = nn + zz * (hold - nn);
                    NH[b*HP + j] = __half_as_ushort(__float2half_rn(hnew));
                }
            }
        }

        __syncthreads();   // h_next complete, visible to all

        // ---- output projection into SMEM ring: out[b,t,:] = h_new @ ow^T + ob ----
        if (tid < 128) {
            const int m = tid >> 1, o = tid & 1;
            float s = ob[o];
            const uint4* hh = (const uint4*)(sm + nxt + (size_t)m*HROW);
            const float* wp = ow + o*256;
            #pragma unroll 8
            for (int i = 0; i < 32; i++) {
                uint4 Hv = hh[i];
                const __half2 h2[4] = {
                    *(const __half2*)&Hv.x, *(const __half2*)&Hv.y,
                    *(const __half2*)&Hv.z, *(const __half2*)&Hv.w };
                const float* wq = wp + i*8;
                #pragma unroll
                for (int q = 0; q < 4; q++) {
                    float2 e = __half22float2(h2[q]);
                    s += e.x * wq[2*q] + e.y * wq[2*q + 1];
                }
            }
            obuf[(m*20 + (t % 20))*2 + o] = s;
        }

        // ---- coalesced flush every 20 steps (180 = 9*20) ----
        if ((t % 20) == 19) {
            __syncthreads();
            const int m = tid >> 2, q = tid & 3;
            float* dst = out + (size_t)(mbase + m)*360 + (t - 19)*2 + q*10;
            const float* src = obuf + m*40 + q*10;
            #pragma unroll
            for (int i = 0; i < 10; i++) dst[i] = src[i];
        }

        uint32_t tmp = cur; cur = nxt; nxt = tmp;
    }
}

extern "C" void kernel_launch(void* const* d_in, const int* in_sizes, int n_in,
                              void* d_out, int out_size)
{
    (void)in_sizes; (void)n_in; (void)out_size;
    const float* z     = (const float*)d_in[0];
    const float* fc_w  = (const float*)d_in[1];
    const float* fc_b  = (const float*)d_in[2];
    /* d_in[3] = w_ih unused: GRU input is all-zeros, gi == b_ih */
    const float* b_ih  = (const float*)d_in[4];
    const float* w_hh  = (const float*)d_in[5];
    const float* b_hh  = (const float*)d_in[6];
    const float* out_w = (const float*)d_in[7];
    const float* out_b = (const float*)d_in[8];

    prep_w<<<96, 256>>>(w_hh);

    cudaFuncSetAttribute(gru_hmma_kernel,
                         cudaFuncAttributeMaxDynamicSharedMemorySize, SMEM_SZ);
    gru_hmma_kernel<<<NCTA, NTHR, SMEM_SZ>>>(
        z, fc_w, fc_b, b_ih, b_hh, out_w, out_b, (float*)d_out);
}

// round 12
// speedup vs baseline: 4.9232x; 1.2929x over previous
#include <cuda_runtime.h>
#include <cuda_fp16.h>
#include <cstdint>

// R10: single-product fp16 GEMM (W quantized to fp16, h in fp16 plane).
// Error budget: h-quant (measured 1.6e-4 in R8) + W-quant (~1-2e-4, independent)
// => predicted 2-4e-4 vs 1e-3 tolerance. MMAs and W L2 traffic both halved vs R8.
// 2-deep A-operand prefetch covers ~250cyc L2 latency (iter time ~200cyc).

#define T_STEPS  180
#define NCTA     128
#define NTHR     256
#define HP       264                 // padded fp16 elems per h row
#define HROW     (HP*2)              // 528 bytes per h row
#define HBUF     (64*HROW)           // 33792 B : one fp16 plane, 64 rows

#define OFF_HA   0
#define OFF_HB   HBUF                // 33792
#define OFF_BSR  (2*HBUF)            // 67584
#define OFF_BSZ  (OFF_BSR+1024)
#define OFF_BIN  (OFF_BSZ+1024)
#define OFF_BHN  (OFF_BIN+1024)
#define OFF_OW   (OFF_BHN+1024)      // 71680
#define OFF_OB   (OFF_OW+2048)
#define OFF_OUT  (OFF_OB+16)         // 64*20*2 f32 = 10240
#define SMEM_SZ  (OFF_OUT+10240)     // 83984 B

// W in HMMA A-fragment order: [g(16)][ks(16)][mt(3)][lane(32)] uint4 (fp16)
__device__ __align__(16) uint4 g_wah[16*16*3*32];

__device__ __forceinline__ uint32_t smem_u32(const void* p) {
    uint32_t a;
    asm("{ .reg .u64 t; cvta.to.shared.u64 t, %1; cvt.u32.u64 %0, t; }" : "=r"(a) : "l"(p));
    return a;
}
__device__ __forceinline__ void ldsm4(uint32_t* r, uint32_t addr) {
    asm volatile("ldmatrix.sync.aligned.m8n8.x4.shared.b16 {%0,%1,%2,%3}, [%4];"
        : "=r"(r[0]), "=r"(r[1]), "=r"(r[2]), "=r"(r[3]) : "r"(addr));
}
__device__ __forceinline__ void mma_f16(float& d0, float& d1, float& d2, float& d3,
                                        uint32_t a0, uint32_t a1, uint32_t a2, uint32_t a3,
                                        uint32_t b0, uint32_t b1) {
    asm volatile("mma.sync.aligned.m16n8k16.row.col.f32.f16.f16.f32 "
        "{%0,%1,%2,%3},{%4,%5,%6,%7},{%8,%9},{%0,%1,%2,%3};"
        : "+f"(d0), "+f"(d1), "+f"(d2), "+f"(d3)
        : "r"(a0), "r"(a1), "r"(a2), "r"(a3), "r"(b0), "r"(b1));
}
__device__ __forceinline__ float sigmoidf_(float x){ return 1.0f/(1.0f + __expf(-x)); }
__device__ __forceinline__ float tanhf_(float x){ return 2.0f/(1.0f + __expf(-2.0f*x)) - 1.0f; }

// ---------- prep: w_hh [768][256] fp32 -> fp16, A-fragment order ----------
__global__ void prep_w(const float* __restrict__ w) {
    int idx = blockIdx.x * 256 + threadIdx.x;         // 96*256 = 24576
    int l  = idx & 31;
    int r1 = idx >> 5;
    int mt = r1 % 3;  r1 /= 3;
    int ks = r1 & 15; int g = r1 >> 4;
    int gr = l >> 2, tig = l & 3;
    uint32_t hreg[4];
    #pragma unroll
    for (int rg = 0; rg < 4; rg++) {
        uint32_t hv = 0;
        #pragma unroll
        for (int hh = 0; hh < 2; hh++) {
            int i   = rg*2 + hh;
            int row = gr + 8*((i >> 1) & 1);
            int col = 2*tig + (i & 1) + 8*(i >> 2);
            float x = w[(mt*256 + g*16 + row)*256 + ks*16 + col];
            hv |= (uint32_t)__half_as_ushort(__float2half_rn(x)) << (16*hh);
        }
        hreg[rg] = hv;
    }
    g_wah[idx] = make_uint4(hreg[0], hreg[1], hreg[2], hreg[3]);
}

__global__ __launch_bounds__(NTHR, 1)
void gru_hmma_kernel(const float* __restrict__ z,
                     const float* __restrict__ fc_w,
                     const float* __restrict__ fc_b,
                     const float* __restrict__ b_ih,
                     const float* __restrict__ b_hh,
                     const float* __restrict__ out_w,
                     const float* __restrict__ out_b,
                     float* __restrict__ out)
{
    extern __shared__ char sm[];
    const uint32_t sbase = smem_u32(sm);
    const int tid = threadIdx.x;
    const int w   = tid >> 5;
    const int l   = tid & 31;
    const int gr  = l >> 2, tig = l & 3;
    const int mbase = blockIdx.x * 64;

    float* bsr = (float*)(sm + OFF_BSR);
    float* bsz = (float*)(sm + OFF_BSZ);
    float* bin = (float*)(sm + OFF_BIN);
    float* bhn = (float*)(sm + OFF_BHN);
    float* ow  = (float*)(sm + OFF_OW);
    float* ob  = (float*)(sm + OFF_OB);
    float* obuf= (float*)(sm + OFF_OUT);

    // biases / output weights
    {
        int i = tid;
        bsr[i] = b_ih[i]       + b_hh[i];
        bsz[i] = b_ih[256 + i] + b_hh[256 + i];
        bin[i] = b_ih[512 + i];
        bhn[i] = b_hh[512 + i];
        ow[i]       = out_w[i];
        ow[256 + i] = out_w[256 + i];
        if (i < 2) ob[i] = out_b[i];
    }

    // ---- stage z [64][128] f32 into HB region, compute h0 into HA (fp16) ----
    {
        float* zs = (float*)(sm + OFF_HB);
        const float4* zp = (const float4*)(z + (size_t)mbase * 128);
        for (int i = tid; i < 2048; i += NTHR) ((float4*)zs)[i] = zp[i];
        __syncthreads();

        const int j = tid;
        float acc[64];
        #pragma unroll
        for (int m = 0; m < 64; m++) acc[m] = 0.f;
        const float* wr = fc_w + (size_t)j * 128;
        for (int k8 = 0; k8 < 16; k8++) {
            float4 wa = *(const float4*)(wr + k8*8);
            float4 wb = *(const float4*)(wr + k8*8 + 4);
            #pragma unroll
            for (int m = 0; m < 64; m++) {
                const float* zr = zs + m*128 + k8*8;
                float4 za = *(const float4*)zr;
                float4 zc = *(const float4*)(zr + 4);
                acc[m] += za.x*wa.x + za.y*wa.y + za.z*wa.z + za.w*wa.w
                        + zc.x*wb.x + zc.y*wb.y + zc.z*wb.z + zc.w*wb.w;
            }
        }
        float fb = fc_b[j];
        unsigned short* HH = (unsigned short*)(sm + OFF_HA);
        for (int m = 0; m < 64; m++) {
            float h = tanhf_(acc[m] + fb);
            HH[m*HP + j] = __half_as_ushort(__float2half_rn(h));
        }
        __syncthreads();
    }

    // per-lane ldmatrix row offset (mapping validated in R6)
    const uint32_t rowoff = (uint32_t)(((l & 7) + 8*((l >> 4) & 1)) * HROW + ((l >> 3) & 1) * 16);

    uint32_t cur = OFF_HA, nxt = OFF_HB;

    for (int t = 0; t < T_STEPS; t++) {
        const uint32_t curb = sbase + cur;

        #pragma unroll 1
        for (int gi = 0; gi < 2; gi++) {
            const int g = w + 8*gi;

            float acc[3][8][4];
            #pragma unroll
            for (int mt = 0; mt < 3; mt++)
                #pragma unroll
                for (int nt = 0; nt < 8; nt++)
                    #pragma unroll
                    for (int r = 0; r < 4; r++) acc[mt][nt][r] = 0.f;

            const uint4* pH = g_wah + (size_t)(g*16)*96 + l;

            // 2-deep A prefetch ring
            uint4 af[2][3];
            af[0][0] = pH[0];       af[0][1] = pH[32];      af[0][2] = pH[64];
            af[1][0] = pH[96];      af[1][1] = pH[96+32];   af[1][2] = pH[96+64];

            #pragma unroll 2
            for (int ks = 0; ks < 16; ks++) {
                const int slot = ks & 1;
                // consume current fragments into temps, then refill slot with ks+2
                uint4 a0 = af[slot][0], a1 = af[slot][1], a2 = af[slot][2];
                if (ks < 14) {
                    const uint4* qH = pH + (ks+2)*96;
                    af[slot][0] = qH[0]; af[slot][1] = qH[32]; af[slot][2] = qH[64];
                }
                // B fragments: h (single fp16 plane), 8 n-tiles at this k-step
                uint32_t bfh[16];
                #pragma unroll
                for (int np = 0; np < 4; np++) {
                    uint32_t r4[4];
                    ldsm4(r4, curb + (uint32_t)(np*(16*HROW) + ks*32) + rowoff);
                    bfh[4*np+0] = r4[0]; bfh[4*np+1] = r4[1];
                    bfh[4*np+2] = r4[2]; bfh[4*np+3] = r4[3];
                }
                // single product: W * h
                mma_f16(acc[0][0][0],acc[0][0][1],acc[0][0][2],acc[0][0][3], a0.x,a0.y,a0.z,a0.w, bfh[0], bfh[1]);
                mma_f16(acc[1][0][0],acc[1][0][1],acc[1][0][2],acc[1][0][3], a1.x,a1.y,a1.z,a1.w, bfh[0], bfh[1]);
                mma_f16(acc[2][0][0],acc[2][0][1],acc[2][0][2],acc[2][0][3], a2.x,a2.y,a2.z,a2.w, bfh[0], bfh[1]);
                #pragma unroll
                for (int nt = 1; nt < 8; nt++) {
                    mma_f16(acc[0][nt][0],acc[0][nt][1],acc[0][nt][2],acc[0][nt][3],
                            a0.x,a0.y,a0.z,a0.w, bfh[2*nt], bfh[2*nt+1]);
                    mma_f16(acc[1][nt][0],acc[1][nt][1],acc[1][nt][2],acc[1][nt][3],
                            a1.x,a1.y,a1.z,a1.w, bfh[2*nt], bfh[2*nt+1]);
                    mma_f16(acc[2][nt][0],acc[2][nt][1],acc[2][nt][2],acc[2][nt][3],
                            a2.x,a2.y,a2.z,a2.w, bfh[2*nt], bfh[2*nt+1]);
                }
            }

            // ---- epilogue: gates + h update, all in registers ----
            const unsigned short* CH = (const unsigned short*)(sm + cur);
            unsigned short* NH = (unsigned short*)(sm + nxt);
            const int jA = 16*g + gr;
            const float brA = bsr[jA], bzA = bsz[jA], biA = bin[jA], bhA = bhn[jA];
            const float brB = bsr[jA+8], bzB = bsz[jA+8], biB = bin[jA+8], bhB = bhn[jA+8];
            #pragma unroll
            for (int r = 0; r < 4; r++) {
                const int j  = jA + 8*(r >> 1);
                const float br = (r >> 1) ? brB : brA;
                const float bz = (r >> 1) ? bzB : bzA;
                const float bi = (r >> 1) ? biB : biA;
                const float bh = (r >> 1) ? bhB : bhA;
                #pragma unroll
                for (int nt = 0; nt < 8; nt++) {
                    const int b = nt*8 + 2*tig + (r & 1);
                    float hold = __half2float(__ushort_as_half(CH[b*HP + j]));
                    float rr = sigmoidf_(acc[0][nt][r] + br);
                    float zz = sigmoidf_(acc[1][nt][r] + bz);
                    float nn = tanhf_(bi + rr * (acc[2][nt][r] + bh));
                    float hnew = nn + zz * (hold - nn);
                    NH[b*HP + j] = __half_as_ushort(__float2half_rn(hnew));
                }
            }
        }

        __syncthreads();   // h_next complete, visible to all

        // ---- output projection into SMEM ring: out[b,t,:] = h_new @ ow^T + ob ----
        if (tid < 128) {
            const int m = tid >> 1, o = tid & 1;
            float s = ob[o];
            const uint4* hh = (const uint4*)(sm + nxt + (size_t)m*HROW);
            const float* wp = ow + o*256;
            #pragma unroll 8
            for (int i = 0; i < 32; i++) {
                uint4 Hv = hh[i];
                const __half2 h2[4] = {
                    *(const __half2*)&Hv.x, *(const __half2*)&Hv.y,
                    *(const __half2*)&Hv.z, *(const __half2*)&Hv.w };
                const float* wq = wp + i*8;
                #pragma unroll
                for (int q = 0; q < 4; q++) {
                    float2 e = __half22float2(h2[q]);
                    s += e.x * wq[2*q] + e.y * wq[2*q + 1];
                }
            }
            obuf[(m*20 + (t % 20))*2 + o] = s;
        }

        // ---- coalesced flush every 20 steps (180 = 9*20) ----
        if ((t % 20) == 19) {
            __syncthreads();
            const int m = tid >> 2, q = tid & 3;
            float* dst = out + (size_t)(mbase + m)*360 + (t - 19)*2 + q*10;
            const float* src = obuf + m*40 + q*10;
            #pragma unroll
            for (int i = 0; i < 10; i++) dst[i] = src[i];
        }

        uint32_t tmp = cur; cur = nxt; nxt = tmp;
    }
}

extern "C" void kernel_launch(void* const* d_in, const int* in_sizes, int n_in,
                              void* d_out, int out_size)
{
    (void)in_sizes; (void)n_in; (void)out_size;
    const float* z     = (const float*)d_in[0];
    const float* fc_w  = (const float*)d_in[1];
    const float* fc_b  = (const float*)d_in[2];
    /* d_in[3] = w_ih unused: GRU input is all-zeros, gi == b_ih */
    const float* b_ih  = (const float*)d_in[4];
    const float* w_hh  = (const float*)d_in[5];
    const float* b_hh  = (const float*)d_in[6];
    const float* out_w = (const float*)d_in[7];
    const float* out_b = (const float*)d_in[8];

    prep_w<<<96, 256>>>(w_hh);

    cudaFuncSetAttribute(gru_hmma_kernel,
                         cudaFuncAttributeMaxDynamicSharedMemorySize, SMEM_SZ);
    gru_hmma_kernel<<<NCTA, NTHR, SMEM_SZ>>>(
        z, fc_w, fc_b, b_ih, b_hh, out_w, out_b, (float*)d_out);
}

// round 13
// speedup vs baseline: 9.8791x; 2.0066x over previous
#include <cuda_runtime.h>
#include <cuda_fp16.h>
#include <cstdint>

// R12: occupancy attack. 256 CTAs x 32 batch rows, 2 CTAs/SM (16 warps/SM) to
// fill the ~19K cyc/step latency bubble diagnosed in R10 (issue=31%, occ=12.5%).
// Gates use HW tanh.approx.f32 (1 MUFU) instead of __expf chains (4x less MUFU).

#define T_STEPS  180
#define NCTA     256
#define NTHR     256
#define MROWS    32                  // batch rows per CTA
#define HP       264                 // padded fp16 elems per h row
#define HROW     (HP*2)              // 528 bytes per h row
#define HBUF     (MROWS*HROW)        // 16896 B : one fp16 plane, 32 rows

#define OFF_HA   0
#define OFF_HB   HBUF                // 16896
#define OFF_BSR  (2*HBUF)            // 33792
#define OFF_BSZ  (OFF_BSR+1024)
#define OFF_BIN  (OFF_BSZ+1024)
#define OFF_BHN  (OFF_BIN+1024)
#define OFF_OW   (OFF_BHN+1024)      // 37888
#define OFF_OB   (OFF_OW+2048)       // 39936
#define OFF_OUT  (OFF_OB+16)         // 39952 ; 32*20*2 f32 = 5120
#define SMEM_SZ  (OFF_OUT+5120)      // 45072 B  (x2 CTAs = 90144 < 228K)

// W in HMMA A-fragment order: [g(16)][ks(16)][mt(3)][lane(32)] uint4 (fp16)
__device__ __align__(16) uint4 g_wah[16*16*3*32];

__device__ __forceinline__ uint32_t smem_u32(const void* p) {
    uint32_t a;
    asm("{ .reg .u64 t; cvta.to.shared.u64 t, %1; cvt.u32.u64 %0, t; }" : "=r"(a) : "l"(p));
    return a;
}
__device__ __forceinline__ void ldsm4(uint32_t* r, uint32_t addr) {
    asm volatile("ldmatrix.sync.aligned.m8n8.x4.shared.b16 {%0,%1,%2,%3}, [%4];"
        : "=r"(r[0]), "=r"(r[1]), "=r"(r[2]), "=r"(r[3]) : "r"(addr));
}
__device__ __forceinline__ void mma_f16(float& d0, float& d1, float& d2, float& d3,
                                        uint32_t a0, uint32_t a1, uint32_t a2, uint32_t a3,
                                        uint32_t b0, uint32_t b1) {
    asm volatile("mma.sync.aligned.m16n8k16.row.col.f32.f16.f16.f32 "
        "{%0,%1,%2,%3},{%4,%5,%6,%7},{%8,%9},{%0,%1,%2,%3};"
        : "+f"(d0), "+f"(d1), "+f"(d2), "+f"(d3)
        : "r"(a0), "r"(a1), "r"(a2), "r"(a3), "r"(b0), "r"(b1));
}
__device__ __forceinline__ float tanh_fast(float x){
    float y; asm("tanh.approx.f32 %0, %1;" : "=f"(y) : "f"(x)); return y;
}
__device__ __forceinline__ float sigmoid_fast(float x){
    return fmaf(tanh_fast(0.5f*x), 0.5f, 0.5f);
}
__device__ __forceinline__ float tanhf_acc(float x){  // accurate (h0 only, off hot path)
    return 2.0f/(1.0f + __expf(-2.0f*x)) - 1.0f;
}

// ---------- prep: w_hh [768][256] fp32 -> fp16, A-fragment order ----------
__global__ void prep_w(const float* __restrict__ w) {
    int idx = blockIdx.x * 256 + threadIdx.x;         // 96*256 = 24576
    int l  = idx & 31;
    int r1 = idx >> 5;
    int mt = r1 % 3;  r1 /= 3;
    int ks = r1 & 15; int g = r1 >> 4;
    int gr = l >> 2, tig = l & 3;
    uint32_t hreg[4];
    #pragma unroll
    for (int rg = 0; rg < 4; rg++) {
        uint32_t hv = 0;
        #pragma unroll
        for (int hh = 0; hh < 2; hh++) {
            int i   = rg*2 + hh;
            int row = gr + 8*((i >> 1) & 1);
            int col = 2*tig + (i & 1) + 8*(i >> 2);
            float x = w[(mt*256 + g*16 + row)*256 + ks*16 + col];
            hv |= (uint32_t)__half_as_ushort(__float2half_rn(x)) << (16*hh);
        }
        hreg[rg] = hv;
    }
    g_wah[idx] = make_uint4(hreg[0], hreg[1], hreg[2], hreg[3]);
}

__global__ __launch_bounds__(NTHR, 2)
void gru_hmma_kernel(const float* __restrict__ z,
                     const float* __restrict__ fc_w,
                     const float* __restrict__ fc_b,
                     const float* __restrict__ b_ih,
                     const float* __restrict__ b_hh,
                     const float* __restrict__ out_w,
                     const float* __restrict__ out_b,
                     float* __restrict__ out)
{
    extern __shared__ char sm[];
    const uint32_t sbase = smem_u32(sm);
    const int tid = threadIdx.x;
    const int w   = tid >> 5;
    const int l   = tid & 31;
    const int gr  = l >> 2, tig = l & 3;
    const int mbase = blockIdx.x * MROWS;

    float* bsr = (float*)(sm + OFF_BSR);
    float* bsz = (float*)(sm + OFF_BSZ);
    float* bin = (float*)(sm + OFF_BIN);
    float* bhn = (float*)(sm + OFF_BHN);
    float* ow  = (float*)(sm + OFF_OW);
    float* ob  = (float*)(sm + OFF_OB);
    float* obuf= (float*)(sm + OFF_OUT);

    // biases / output weights
    {
        int i = tid;
        bsr[i] = b_ih[i]       + b_hh[i];
        bsz[i] = b_ih[256 + i] + b_hh[256 + i];
        bin[i] = b_ih[512 + i];
        bhn[i] = b_hh[512 + i];
        ow[i]       = out_w[i];
        ow[256 + i] = out_w[256 + i];
        if (i < 2) ob[i] = out_b[i];
    }

    // ---- stage z [32][128] f32 into HB region, compute h0 into HA (fp16) ----
    {
        float* zs = (float*)(sm + OFF_HB);
        const float4* zp = (const float4*)(z + (size_t)mbase * 128);
        for (int i = tid; i < 1024; i += NTHR) ((float4*)zs)[i] = zp[i];
        __syncthreads();

        const int j = tid;
        float acc[MROWS];
        #pragma unroll
        for (int m = 0; m < MROWS; m++) acc[m] = 0.f;
        const float* wr = fc_w + (size_t)j * 128;
        for (int k8 = 0; k8 < 16; k8++) {
            float4 wa = *(const float4*)(wr + k8*8);
            float4 wb = *(const float4*)(wr + k8*8 + 4);
            #pragma unroll
            for (int m = 0; m < MROWS; m++) {
                const float* zr = zs + m*128 + k8*8;
                float4 za = *(const float4*)zr;
                float4 zc = *(const float4*)(zr + 4);
                acc[m] += za.x*wa.x + za.y*wa.y + za.z*wa.z + za.w*wa.w
                        + zc.x*wb.x + zc.y*wb.y + zc.z*wb.z + zc.w*wb.w;
            }
        }
        float fb = fc_b[j];
        unsigned short* HH = (unsigned short*)(sm + OFF_HA);
        for (int m = 0; m < MROWS; m++) {
            float h = tanhf_acc(acc[m] + fb);
            HH[m*HP + j] = __half_as_ushort(__float2half_rn(h));
        }
        __syncthreads();
    }

    // per-lane ldmatrix row offset (mapping validated in R6)
    const uint32_t rowoff = (uint32_t)(((l & 7) + 8*((l >> 4) & 1)) * HROW + ((l >> 3) & 1) * 16);

    uint32_t cur = OFF_HA, nxt = OFF_HB;

    for (int t = 0; t < T_STEPS; t++) {
        const uint32_t curb = sbase + cur;

        #pragma unroll 1
        for (int gi = 0; gi < 2; gi++) {
            const int g = w + 8*gi;

            float acc[3][4][4];
            #pragma unroll
            for (int mt = 0; mt < 3; mt++)
                #pragma unroll
                for (int nt = 0; nt < 4; nt++)
                    #pragma unroll
                    for (int r = 0; r < 4; r++) acc[mt][nt][r] = 0.f;

            const uint4* pH = g_wah + (size_t)(g*16)*96 + l;

            // 2-deep A prefetch ring
            uint4 af[2][3];
            af[0][0] = pH[0];       af[0][1] = pH[32];      af[0][2] = pH[64];
            af[1][0] = pH[96];      af[1][1] = pH[96+32];   af[1][2] = pH[96+64];

            #pragma unroll 2
            for (int ks = 0; ks < 16; ks++) {
                const int slot = ks & 1;
                uint4 a0 = af[slot][0], a1 = af[slot][1], a2 = af[slot][2];
                if (ks < 14) {
                    const uint4* qH = pH + (ks+2)*96;
                    af[slot][0] = qH[0]; af[slot][1] = qH[32]; af[slot][2] = qH[64];
                }
                // B fragments: 32 batch rows = 2 ldsm4 (4 n-tiles)
                uint32_t bfh[8];
                #pragma unroll
                for (int np = 0; np < 2; np++) {
                    uint32_t r4[4];
                    ldsm4(r4, curb + (uint32_t)(np*(16*HROW) + ks*32) + rowoff);
                    bfh[4*np+0] = r4[0]; bfh[4*np+1] = r4[1];
                    bfh[4*np+2] = r4[2]; bfh[4*np+3] = r4[3];
                }
                #pragma unroll
                for (int nt = 0; nt < 4; nt++) {
                    mma_f16(acc[0][nt][0],acc[0][nt][1],acc[0][nt][2],acc[0][nt][3],
                            a0.x,a0.y,a0.z,a0.w, bfh[2*nt], bfh[2*nt+1]);
                    mma_f16(acc[1][nt][0],acc[1][nt][1],acc[1][nt][2],acc[1][nt][3],
                            a1.x,a1.y,a1.z,a1.w, bfh[2*nt], bfh[2*nt+1]);
                    mma_f16(acc[2][nt][0],acc[2][nt][1],acc[2][nt][2],acc[2][nt][3],
                            a2.x,a2.y,a2.z,a2.w, bfh[2*nt], bfh[2*nt+1]);
                }
            }

            // ---- epilogue: gates + h update, all in registers ----
            const unsigned short* CH = (const unsigned short*)(sm + cur);
            unsigned short* NH = (unsigned short*)(sm + nxt);
            const int jA = 16*g + gr;
            const float brA = bsr[jA], bzA = bsz[jA], biA = bin[jA], bhA = bhn[jA];
            const float brB = bsr[jA+8], bzB = bsz[jA+8], biB = bin[jA+8], bhB = bhn[jA+8];
            #pragma unroll
            for (int r = 0; r < 4; r++) {
                const int j  = jA + 8*(r >> 1);
                const float br = (r >> 1) ? brB : brA;
                const float bz = (r >> 1) ? bzB : bzA;
                const float bi = (r >> 1) ? biB : biA;
                const float bh = (r >> 1) ? bhB : bhA;
                #pragma unroll
                for (int nt = 0; nt < 4; nt++) {
                    const int b = nt*8 + 2*tig + (r & 1);
                    float hold = __half2float(__ushort_as_half(CH[b*HP + j]));
                    float rr = sigmoid_fast(acc[0][nt][r] + br);
                    float zz = sigmoid_fast(acc[1][nt][r] + bz);
                    float nn = tanh_fast(bi + rr * (acc[2][nt][r] + bh));
                    float hnew = nn + zz * (hold - nn);
                    NH[b*HP + j] = __half_as_ushort(__float2half_rn(hnew));
                }
            }
        }

        __syncthreads();   // h_next complete, visible to all

        // ---- output projection into SMEM ring: out[b,t,:] = h_new @ ow^T + ob ----
        if (tid < 2*MROWS) {
            const int m = tid >> 1, o = tid & 1;
            float s = ob[o];
            const uint4* hh = (const uint4*)(sm + nxt + (size_t)m*HROW);
            const float* wp = ow + o*256;
            #pragma unroll 8
            for (int i = 0; i < 32; i++) {
                uint4 Hv = hh[i];
                const __half2 h2[4] = {
                    *(const __half2*)&Hv.x, *(const __half2*)&Hv.y,
                    *(const __half2*)&Hv.z, *(const __half2*)&Hv.w };
                const float* wq = wp + i*8;
                #pragma unroll
                for (int q = 0; q < 4; q++) {
                    float2 e = __half22float2(h2[q]);
                    s += e.x * wq[2*q] + e.y * wq[2*q + 1];
                }
            }
            obuf[(m*20 + (t % 20))*2 + o] = s;
        }

        // ---- coalesced flush every 20 steps (180 = 9*20) ----
        if ((t % 20) == 19) {
            __syncthreads();
            const int m = tid >> 3, q = tid & 7;   // 32 rows x 8 threads
            float* dst = out + (size_t)(mbase + m)*360 + (t - 19)*2 + q*5;
            const float* src = obuf + m*40 + q*5;
            #pragma unroll
            for (int i = 0; i < 5; i++) dst[i] = src[i];
        }

        uint32_t tmp = cur; cur = nxt; nxt = tmp;
    }
}

extern "C" void kernel_launch(void* const* d_in, const int* in_sizes, int n_in,
                              void* d_out, int out_size)
{
    (void)in_sizes; (void)n_in; (void)out_size;
    const float* z     = (const float*)d_in[0];
    const float* fc_w  = (const float*)d_in[1];
    const float* fc_b  = (const float*)d_in[2];
    /* d_in[3] = w_ih unused: GRU input is all-zeros, gi == b_ih */
    const float* b_ih  = (const float*)d_in[4];
    const float* w_hh  = (const float*)d_in[5];
    const float* b_hh  = (const float*)d_in[6];
    const float* out_w = (const float*)d_in[7];
    const float* out_b = (const float*)d_in[8];

    prep_w<<<96, 256>>>(w_hh);

    cudaFuncSetAttribute(gru_hmma_kernel,
                         cudaFuncAttributeMaxDynamicSharedMemorySize, SMEM_SZ);
    gru_hmma_kernel<<<NCTA, NTHR, SMEM_SZ>>>(
        z, fc_w, fc_b, b_ih, b_hh, out_w, out_b, (float*)d_out);
}

// round 15
// speedup vs baseline: 10.9245x; 1.1058x over previous
#include <cuda_runtime.h>
#include <cuda_fp16.h>
#include <cstdint>

// R14 = R13 resubmit (R13 bench was an infra failure: container died twice,
// kernel never measured).
//  - f16x2 epilogue: tanh.approx.f16x2 on packed (b,b+1) pairs -> MUFU halved,
//    gate update in HFMA2/HSUB2. Predicted rel_err 3-5e-4 (tol 1e-3).
//  - cross-tile A-fragment prefetch: next tile's W LDGs issued before the
//    epilogue, hiding L2 latency behind ~350 epilogue instructions.

#define T_STEPS  180
#define NCTA     256
#define NTHR     256
#define MROWS    32                  // batch rows per CTA
#define HP       264                 // padded fp16 elems per h row
#define HROW     (HP*2)              // 528 bytes per h row
#define HBUF     (MROWS*HROW)        // 16896 B : one fp16 plane, 32 rows

#define OFF_HA   0
#define OFF_HB   HBUF                // 16896
#define OFF_BSR  (2*HBUF)            // 33792
#define OFF_BSZ  (OFF_BSR+1024)
#define OFF_BIN  (OFF_BSZ+1024)
#define OFF_BHN  (OFF_BIN+1024)
#define OFF_OW   (OFF_BHN+1024)      // 37888
#define OFF_OB   (OFF_OW+2048)       // 39936
#define OFF_OUT  (OFF_OB+16)         // 39952 ; 32*20*2 f32 = 5120
#define SMEM_SZ  (OFF_OUT+5120)      // 45072 B  (x2 CTAs = 90144)

// W in HMMA A-fragment order: [g(16)][ks(16)][mt(3)][lane(32)] uint4 (fp16)
__device__ __align__(16) uint4 g_wah[16*16*3*32];

__device__ __forceinline__ uint32_t smem_u32(const void* p) {
    uint32_t a;
    asm("{ .reg .u64 t; cvta.to.shared.u64 t, %1; cvt.u32.u64 %0, t; }" : "=r"(a) : "l"(p));
    return a;
}
__device__ __forceinline__ void ldsm4(uint32_t* r, uint32_t addr) {
    asm volatile("ldmatrix.sync.aligned.m8n8.x4.shared.b16 {%0,%1,%2,%3}, [%4];"
        : "=r"(r[0]), "=r"(r[1]), "=r"(r[2]), "=r"(r[3]) : "r"(addr));
}
__device__ __forceinline__ void mma_f16(float& d0, float& d1, float& d2, float& d3,
                                        uint32_t a0, uint32_t a1, uint32_t a2, uint32_t a3,
                                        uint32_t b0, uint32_t b1) {
    asm volatile("mma.sync.aligned.m16n8k16.row.col.f32.f16.f16.f32 "
        "{%0,%1,%2,%3},{%4,%5,%6,%7},{%8,%9},{%0,%1,%2,%3};"
        : "+f"(d0), "+f"(d1), "+f"(d2), "+f"(d3)
        : "r"(a0), "r"(a1), "r"(a2), "r"(a3), "r"(b0), "r"(b1));
}
__device__ __forceinline__ __half2 tanh2(__half2 x){
    uint32_t xi = *reinterpret_cast<uint32_t*>(&x), yi;
    asm("tanh.approx.f16x2 %0, %1;" : "=r"(yi) : "r"(xi));
    return *reinterpret_cast<__half2*>(&yi);
}
__device__ __forceinline__ float tanhf_acc(float x){  // accurate (h0 only)
    return 2.0f/(1.0f + __expf(-2.0f*x)) - 1.0f;
}

// ---------- prep: w_hh [768][256] fp32 -> fp16, A-fragment order ----------
__global__ void prep_w(const float* __restrict__ w) {
    int idx = blockIdx.x * 256 + threadIdx.x;         // 96*256 = 24576
    int l  = idx & 31;
    int r1 = idx >> 5;
    int mt = r1 % 3;  r1 /= 3;
    int ks = r1 & 15; int g = r1 >> 4;
    int gr = l >> 2, tig = l & 3;
    uint32_t hreg[4];
    #pragma unroll
    for (int rg = 0; rg < 4; rg++) {
        uint32_t hv = 0;
        #pragma unroll
        for (int hh = 0; hh < 2; hh++) {
            int i   = rg*2 + hh;
            int row = gr + 8*((i >> 1) & 1);
            int col = 2*tig + (i & 1) + 8*(i >> 2);
            float x = w[(mt*256 + g*16 + row)*256 + ks*16 + col];
            hv |= (uint32_t)__half_as_ushort(__float2half_rn(x)) << (16*hh);
        }
        hreg[rg] = hv;
    }
    g_wah[idx] = make_uint4(hreg[0], hreg[1], hreg[2], hreg[3]);
}

__global__ __launch_bounds__(NTHR, 2)
void gru_hmma_kernel(const float* __restrict__ z,
                     const float* __restrict__ fc_w,
                     const float* __restrict__ fc_b,
                     const float* __restrict__ b_ih,
                     const float* __restrict__ b_hh,
                     const float* __restrict__ out_w,
                     const float* __restrict__ out_b,
                     float* __restrict__ out)
{
    extern __shared__ char sm[];
    const uint32_t sbase = smem_u32(sm);
    const int tid = threadIdx.x;
    const int w   = tid >> 5;
    const int l   = tid & 31;
    const int gr  = l >> 2, tig = l & 3;
    const int mbase = blockIdx.x * MROWS;

    float* bsr = (float*)(sm + OFF_BSR);
    float* bsz = (float*)(sm + OFF_BSZ);
    float* bin = (float*)(sm + OFF_BIN);
    float* bhn = (float*)(sm + OFF_BHN);
    float* ow  = (float*)(sm + OFF_OW);
    float* ob  = (float*)(sm + OFF_OB);
    float* obuf= (float*)(sm + OFF_OUT);

    // biases / output weights
    {
        int i = tid;
        bsr[i] = b_ih[i]       + b_hh[i];
        bsz[i] = b_ih[256 + i] + b_hh[256 + i];
        bin[i] = b_ih[512 + i];
        bhn[i] = b_hh[512 + i];
        ow[i]       = out_w[i];
        ow[256 + i] = out_w[256 + i];
        if (i < 2) ob[i] = out_b[i];
    }

    // ---- stage z [32][128] f32 into HB region, compute h0 into HA (fp16) ----
    {
        float* zs = (float*)(sm + OFF_HB);
        const float4* zp = (const float4*)(z + (size_t)mbase * 128);
        for (int i = tid; i < 1024; i += NTHR) ((float4*)zs)[i] = zp[i];
        __syncthreads();

        const int j = tid;
        float acc[MROWS];
        #pragma unroll
        for (int m = 0; m < MROWS; m++) acc[m] = 0.f;
        const float* wr = fc_w + (size_t)j * 128;
        for (int k8 = 0; k8 < 16; k8++) {
            float4 wa = *(const float4*)(wr + k8*8);
            float4 wb = *(const float4*)(wr + k8*8 + 4);
            #pragma unroll
            for (int m = 0; m < MROWS; m++) {
                const float* zr = zs + m*128 + k8*8;
                float4 za = *(const float4*)zr;
                float4 zc = *(const float4*)(zr + 4);
                acc[m] += za.x*wa.x + za.y*wa.y + za.z*wa.z + za.w*wa.w
                        + zc.x*wb.x + zc.y*wb.y + zc.z*wb.z + zc.w*wb.w;
            }
        }
        float fb = fc_b[j];
        unsigned short* HH = (unsigned short*)(sm + OFF_HA);
        for (int m = 0; m < MROWS; m++) {
            float h = tanhf_acc(acc[m] + fb);
            HH[m*HP + j] = __half_as_ushort(__float2half_rn(h));
        }
        __syncthreads();
    }

    // per-lane ldmatrix row offset (mapping validated in R6)
    const uint32_t rowoff = (uint32_t)(((l & 7) + 8*((l >> 4) & 1)) * HROW + ((l >> 3) & 1) * 16);

    const uint4* pH0 = g_wah + (size_t)(w*16)*96 + l;        // gi=0 tile (g = w)
    const uint4* pH1 = g_wah + (size_t)((w+8)*16)*96 + l;    // gi=1 tile (g = w+8)
    const __half2 h05 = __floats2half2_rn(0.5f, 0.5f);

    uint32_t cur = OFF_HA, nxt = OFF_HB;

    // prime A-fragment ring for t=0, gi=0
    uint4 af[2][3];
    af[0][0] = pH0[0];    af[0][1] = pH0[32];    af[0][2] = pH0[64];
    af[1][0] = pH0[96];   af[1][1] = pH0[96+32]; af[1][2] = pH0[96+64];

    for (int t = 0; t < T_STEPS; t++) {
        const uint32_t curb = sbase + cur;

        #pragma unroll 1
        for (int gi = 0; gi < 2; gi++) {
            const int g = w + 8*gi;
            const uint4* pH    = gi ? pH1 : pH0;
            const uint4* pNext = gi ? pH0 : pH1;   // next tile (or next step's gi=0)

            float acc[3][4][4];
            #pragma unroll
            for (int mt = 0; mt < 3; mt++)
                #pragma unroll
                for (int nt = 0; nt < 4; nt++)
                    #pragma unroll
                    for (int r = 0; r < 4; r++) acc[mt][nt][r] = 0.f;

            #pragma unroll 4
            for (int ks = 0; ks < 16; ks++) {
                const int slot = ks & 1;
                uint4 a0 = af[slot][0], a1 = af[slot][1], a2 = af[slot][2];
                if (ks < 14) {
                    const uint4* qH = pH + (ks+2)*96;
                    af[slot][0] = qH[0]; af[slot][1] = qH[32]; af[slot][2] = qH[64];
                }
                // B fragments: 32 batch rows = 2 ldsm4 (4 n-tiles)
                uint32_t bfh[8];
                #pragma unroll
                for (int np = 0; np < 2; np++) {
                    uint32_t r4[4];
                    ldsm4(r4, curb + (uint32_t)(np*(16*HROW) + ks*32) + rowoff);
                    bfh[4*np+0] = r4[0]; bfh[4*np+1] = r4[1];
                    bfh[4*np+2] = r4[2]; bfh[4*np+3] = r4[3];
                }
                #pragma unroll
                for (int nt = 0; nt < 4; nt++) {
                    mma_f16(acc[0][nt][0],acc[0][nt][1],acc[0][nt][2],acc[0][nt][3],
                            a0.x,a0.y,a0.z,a0.w, bfh[2*nt], bfh[2*nt+1]);
                    mma_f16(acc[1][nt][0],acc[1][nt][1],acc[1][nt][2],acc[1][nt][3],
                            a1.x,a1.y,a1.z,a1.w, bfh[2*nt], bfh[2*nt+1]);
                    mma_f16(acc[2][nt][0],acc[2][nt][1],acc[2][nt][2],acc[2][nt][3],
                            a2.x,a2.y,a2.z,a2.w, bfh[2*nt], bfh[2*nt+1]);
                }
            }

            // refill A ring for the NEXT tile now; LDG latency hides behind epilogue
            af[0][0] = pNext[0];    af[0][1] = pNext[32];    af[0][2] = pNext[64];
            af[1][0] = pNext[96];   af[1][1] = pNext[96+32]; af[1][2] = pNext[96+64];

            // ---- epilogue: f16x2 gates + h update on (b, b+1) pairs ----
            const unsigned short* CH = (const unsigned short*)(sm + cur);
            unsigned short* NH = (unsigned short*)(sm + nxt);
            const int jA = 16*g + gr;
            #pragma unroll
            for (int rp = 0; rp < 2; rp++) {
                const int j = jA + 8*rp;
                const float  br05 = 0.5f*bsr[j], bz05 = 0.5f*bsz[j];
                const float  bh   = bhn[j];
                const __half2 bi2 = __float2half2_rn(bin[j]);
                #pragma unroll
                for (int nt = 0; nt < 4; nt++) {
                    const int b0 = nt*8 + 2*tig;
                    const float ar0 = acc[0][nt][2*rp],   ar1 = acc[0][nt][2*rp+1];
                    const float az0 = acc[1][nt][2*rp],   az1 = acc[1][nt][2*rp+1];
                    const float an0 = acc[2][nt][2*rp],   an1 = acc[2][nt][2*rp+1];
                    // sigmoid(x) = 0.5*tanh(0.5x)+0.5, pair-packed
                    __half2 rr2 = __hfma2(tanh2(__floats2half2_rn(
                                      fmaf(ar0, 0.5f, br05), fmaf(ar1, 0.5f, br05))), h05, h05);
                    __half2 zz2 = __hfma2(tanh2(__floats2half2_rn(
                                      fmaf(az0, 0.5f, bz05), fmaf(az1, 0.5f, bz05))), h05, h05);
                    __half2 tn2 = __floats2half2_rn(an0 + bh, an1 + bh);
                    __half2 nn2 = tanh2(__hfma2(rr2, tn2, bi2));
                    // hold pair
                    uint32_t hw = (uint32_t)CH[b0*HP + j] | ((uint32_t)CH[(b0+1)*HP + j] << 16);
                    __half2 hold2 = *reinterpret_cast<__half2*>(&hw);
                    __half2 hnew2 = __hfma2(zz2, __hsub2(hold2, nn2), nn2);
                    uint32_t hv = *reinterpret_cast<uint32_t*>(&hnew2);
                    NH[b0*HP + j]     = (unsigned short)(hv & 0xffffu);
                    NH[(b0+1)*HP + j] = (unsigned short)(hv >> 16);
                }
            }
        }

        __syncthreads();   // h_next complete, visible to all

        // ---- output projection into SMEM ring: out[b,t,:] = h_new @ ow^T + ob ----
        if (tid < 2*MROWS) {
            const int m = tid >> 1, o = tid & 1;
            float s = ob[o];
            const uint4* hh = (const uint4*)(sm + nxt + (size_t)m*HROW);
            const float* wp = ow + o*256;
            #pragma unroll 8
            for (int i = 0; i < 32; i++) {
                uint4 Hv = hh[i];
                const __half2 h2[4] = {
                    *(const __half2*)&Hv.x, *(const __half2*)&Hv.y,
                    *(const __half2*)&Hv.z, *(const __half2*)&Hv.w };
                const float* wq = wp + i*8;
                #pragma unroll
                for (int q = 0; q < 4; q++) {
                    float2 e = __half22float2(h2[q]);
                    s += e.x * wq[2*q] + e.y * wq[2*q + 1];
                }
            }
            obuf[(m*20 + (t % 20))*2 + o] = s;
        }

        // ---- coalesced flush every 20 steps (180 = 9*20) ----
        if ((t % 20) == 19) {
            __syncthreads();
            const int m = tid >> 3, q = tid & 7;   // 32 rows x 8 threads
            float* dst = out + (size_t)(mbase + m)*360 + (t - 19)*2 + q*5;
            const float* src = obuf + m*40 + q*5;
            #pragma unroll
            for (int i = 0; i < 5; i++) dst[i] = src[i];
        }

        uint32_t tmp = cur; cur = nxt; nxt = tmp;
    }
}

extern "C" void kernel_launch(void* const* d_in, const int* in_sizes, int n_in,
                              void* d_out, int out_size)
{
    (void)in_sizes; (void)n_in; (void)out_size;
    const float* z     = (const float*)d_in[0];
    const float* fc_w  = (const float*)d_in[1];
    const float* fc_b  = (const float*)d_in[2];
    /* d_in[3] = w_ih unused: GRU input is all-zeros, gi == b_ih */
    const float* b_ih  = (const float*)d_in[4];
    const float* w_hh  = (const float*)d_in[5];
    const float* b_hh  = (const float*)d_in[6];
    const float* out_w = (const float*)d_in[7];
    const float* out_b = (const float*)d_in[8];

    prep_w<<<96, 256>>>(w_hh);

    cudaFuncSetAttribute(gru_hmma_kernel,
                         cudaFuncAttributeMaxDynamicSharedMemorySize, SMEM_SZ);
    gru_hmma_kernel<<<NCTA, NTHR, SMEM_SZ>>>(
        z, fc_w, fc_b, b_ih, b_hh, out_w, out_b, (float*)d_out);
}

// round 16
// speedup vs baseline: 10.9708x; 1.0042x over previous
#include <cuda_runtime.h>
#include <cuda_fp16.h>
#include <cstdint>

// R15: anti-phase CTA stagger + f16x2 epilogue trim.
//  - co-resident CTA pairs are (b, b+148) (classic LUT placement). Delaying
//    bid>=148 by ~half a step breaks the phase-lock so one CTA's MMA stream
//    covers the other's epilogue/barrier (tensor was idle in both at once).
//  - epilogue: pack acc to half2 first, all bias/scale math in HFMA2/HADD2.

#define T_STEPS  180
#define NCTA     256
#define NTHR     256
#define MROWS    32                  // batch rows per CTA
#define HP       264                 // padded fp16 elems per h row
#define HROW     (HP*2)              // 528 bytes per h row
#define HBUF     (MROWS*HROW)        // 16896 B : one fp16 plane, 32 rows

#define OFF_HA   0
#define OFF_HB   HBUF                // 16896
#define OFF_BSR  (2*HBUF)            // 33792
#define OFF_BSZ  (OFF_BSR+1024)
#define OFF_BIN  (OFF_BSZ+1024)
#define OFF_BHN  (OFF_BIN+1024)
#define OFF_OW   (OFF_BHN+1024)      // 37888
#define OFF_OB   (OFF_OW+2048)       // 39936
#define OFF_OUT  (OFF_OB+16)         // 39952 ; 32*20*2 f32 = 5120
#define SMEM_SZ  (OFF_OUT+5120)      // 45072 B  (x2 CTAs = 90144)

// W in HMMA A-fragment order: [g(16)][ks(16)][mt(3)][lane(32)] uint4 (fp16)
__device__ __align__(16) uint4 g_wah[16*16*3*32];

__device__ __forceinline__ uint32_t smem_u32(const void* p) {
    uint32_t a;
    asm("{ .reg .u64 t; cvta.to.shared.u64 t, %1; cvt.u32.u64 %0, t; }" : "=r"(a) : "l"(p));
    return a;
}
__device__ __forceinline__ void ldsm4(uint32_t* r, uint32_t addr) {
    asm volatile("ldmatrix.sync.aligned.m8n8.x4.shared.b16 {%0,%1,%2,%3}, [%4];"
        : "=r"(r[0]), "=r"(r[1]), "=r"(r[2]), "=r"(r[3]) : "r"(addr));
}
__device__ __forceinline__ void mma_f16(float& d0, float& d1, float& d2, float& d3,
                                        uint32_t a0, uint32_t a1, uint32_t a2, uint32_t a3,
                                        uint32_t b0, uint32_t b1) {
    asm volatile("mma.sync.aligned.m16n8k16.row.col.f32.f16.f16.f32 "
        "{%0,%1,%2,%3},{%4,%5,%6,%7},{%8,%9},{%0,%1,%2,%3};"
        : "+f"(d0), "+f"(d1), "+f"(d2), "+f"(d3)
        : "r"(a0), "r"(a1), "r"(a2), "r"(a3), "r"(b0), "r"(b1));
}
__device__ __forceinline__ __half2 tanh2(__half2 x){
    uint32_t xi = *reinterpret_cast<uint32_t*>(&x), yi;
    asm("tanh.approx.f16x2 %0, %1;" : "=r"(yi) : "r"(xi));
    return *reinterpret_cast<__half2*>(&yi);
}
__device__ __forceinline__ float tanhf_acc(float x){  // accurate (h0 only)
    return 2.0f/(1.0f + __expf(-2.0f*x)) - 1.0f;
}

// ---------- prep: w_hh [768][256] fp32 -> fp16, A-fragment order ----------
__global__ void prep_w(const float* __restrict__ w) {
    int idx = blockIdx.x * 256 + threadIdx.x;         // 96*256 = 24576
    int l  = idx & 31;
    int r1 = idx >> 5;
    int mt = r1 % 3;  r1 /= 3;
    int ks = r1 & 15; int g = r1 >> 4;
    int gr = l >> 2, tig = l & 3;
    uint32_t hreg[4];
    #pragma unroll
    for (int rg = 0; rg < 4; rg++) {
        uint32_t hv = 0;
        #pragma unroll
        for (int hh = 0; hh < 2; hh++) {
            int i   = rg*2 + hh;
            int row = gr + 8*((i >> 1) & 1);
            int col = 2*tig + (i & 1) + 8*(i >> 2);
            float x = w[(mt*256 + g*16 + row)*256 + ks*16 + col];
            hv |= (uint32_t)__half_as_ushort(__float2half_rn(x)) << (16*hh);
        }
        hreg[rg] = hv;
    }
    g_wah[idx] = make_uint4(hreg[0], hreg[1], hreg[2], hreg[3]);
}

__global__ __launch_bounds__(NTHR, 2)
void gru_hmma_kernel(const float* __restrict__ z,
                     const float* __restrict__ fc_w,
                     const float* __restrict__ fc_b,
                     const float* __restrict__ b_ih,
                     const float* __restrict__ b_hh,
                     const float* __restrict__ out_w,
                     const float* __restrict__ out_b,
                     float* __restrict__ out)
{
    extern __shared__ char sm[];
    const uint32_t sbase = smem_u32(sm);
    const int tid = threadIdx.x;
    const int w   = tid >> 5;
    const int l   = tid & 31;
    const int gr  = l >> 2, tig = l & 3;
    const int mbase = blockIdx.x * MROWS;

    float* bsr = (float*)(sm + OFF_BSR);
    float* bsz = (float*)(sm + OFF_BSZ);
    float* bin = (float*)(sm + OFF_BIN);
    float* bhn = (float*)(sm + OFF_BHN);
    float* ow  = (float*)(sm + OFF_OW);
    float* ob  = (float*)(sm + OFF_OB);
    float* obuf= (float*)(sm + OFF_OUT);

    // biases / output weights
    {
        int i = tid;
        bsr[i] = b_ih[i]       + b_hh[i];
        bsz[i] = b_ih[256 + i] + b_hh[256 + i];
        bin[i] = b_ih[512 + i];
        bhn[i] = b_hh[512 + i];
        ow[i]       = out_w[i];
        ow[256 + i] = out_w[256 + i];
        if (i < 2) ob[i] = out_b[i];
    }

    // ---- stage z [32][128] f32 into HB region, compute h0 into HA (fp16) ----
    {
        float* zs = (float*)(sm + OFF_HB);
        const float4* zp = (const float4*)(z + (size_t)mbase * 128);
        for (int i = tid; i < 1024; i += NTHR) ((float4*)zs)[i] = zp[i];
        __syncthreads();

        const int j = tid;
        float acc[MROWS];
        #pragma unroll
        for (int m = 0; m < MROWS; m++) acc[m] = 0.f;
        const float* wr = fc_w + (size_t)j * 128;
        for (int k8 = 0; k8 < 16; k8++) {
            float4 wa = *(const float4*)(wr + k8*8);
            float4 wb = *(const float4*)(wr + k8*8 + 4);
            #pragma unroll
            for (int m = 0; m < MROWS; m++) {
                const float* zr = zs + m*128 + k8*8;
                float4 za = *(const float4*)zr;
                float4 zc = *(const float4*)(zr + 4);
                acc[m] += za.x*wa.x + za.y*wa.y + za.z*wa.z + za.w*wa.w
                        + zc.x*wb.x + zc.y*wb.y + zc.z*wb.z + zc.w*wb.w;
            }
        }
        float fb = fc_b[j];
        unsigned short* HH = (unsigned short*)(sm + OFF_HA);
        for (int m = 0; m < MROWS; m++) {
            float h = tanhf_acc(acc[m] + fb);
            HH[m*HP + j] = __half_as_ushort(__float2half_rn(h));
        }
        __syncthreads();
    }

    // ---- anti-phase stagger: delay the second co-resident CTA of each SM ----
    // 256 CTAs: pairs (b, b+148) share an SM. ~8000 cyc ~= half a GRU step.
    if (blockIdx.x >= 148) {
        unsigned long long s0 = clock64();
        while (clock64() - s0 < 8000ull) {}
    }

    // per-lane ldmatrix row offset (mapping validated in R6)
    const uint32_t rowoff = (uint32_t)(((l & 7) + 8*((l >> 4) & 1)) * HROW + ((l >> 3) & 1) * 16);

    const uint4* pH0 = g_wah + (size_t)(w*16)*96 + l;        // gi=0 tile (g = w)
    const uint4* pH1 = g_wah + (size_t)((w+8)*16)*96 + l;    // gi=1 tile (g = w+8)
    const __half2 h05 = __floats2half2_rn(0.5f, 0.5f);

    uint32_t cur = OFF_HA, nxt = OFF_HB;

    // prime A-fragment ring for t=0, gi=0
    uint4 af[2][3];
    af[0][0] = pH0[0];    af[0][1] = pH0[32];    af[0][2] = pH0[64];
    af[1][0] = pH0[96];   af[1][1] = pH0[96+32]; af[1][2] = pH0[96+64];

    for (int t = 0; t < T_STEPS; t++) {
        const uint32_t curb = sbase + cur;

        #pragma unroll 1
        for (int gi = 0; gi < 2; gi++) {
            const int g = w + 8*gi;
            const uint4* pH    = gi ? pH1 : pH0;
            const uint4* pNext = gi ? pH0 : pH1;   // next tile (or next step's gi=0)

            float acc[3][4][4];
            #pragma unroll
            for (int mt = 0; mt < 3; mt++)
                #pragma unroll
                for (int nt = 0; nt < 4; nt++)
                    #pragma unroll
                    for (int r = 0; r < 4; r++) acc[mt][nt][r] = 0.f;

            #pragma unroll 4
            for (int ks = 0; ks < 16; ks++) {
                const int slot = ks & 1;
                uint4 a0 = af[slot][0], a1 = af[slot][1], a2 = af[slot][2];
                if (ks < 14) {
                    const uint4* qH = pH + (ks+2)*96;
                    af[slot][0] = qH[0]; af[slot][1] = qH[32]; af[slot][2] = qH[64];
                }
                // B fragments: 32 batch rows = 2 ldsm4 (4 n-tiles)
                uint32_t bfh[8];
                #pragma unroll
                for (int np = 0; np < 2; np++) {
                    uint32_t r4[4];
                    ldsm4(r4, curb + (uint32_t)(np*(16*HROW) + ks*32) + rowoff);
                    bfh[4*np+0] = r4[0]; bfh[4*np+1] = r4[1];
                    bfh[4*np+2] = r4[2]; bfh[4*np+3] = r4[3];
                }
                #pragma unroll
                for (int nt = 0; nt < 4; nt++) {
                    mma_f16(acc[0][nt][0],acc[0][nt][1],acc[0][nt][2],acc[0][nt][3],
                            a0.x,a0.y,a0.z,a0.w, bfh[2*nt], bfh[2*nt+1]);
                    mma_f16(acc[1][nt][0],acc[1][nt][1],acc[1][nt][2],acc[1][nt][3],
                            a1.x,a1.y,a1.z,a1.w, bfh[2*nt], bfh[2*nt+1]);
                    mma_f16(acc[2][nt][0],acc[2][nt][1],acc[2][nt][2],acc[2][nt][3],
                            a2.x,a2.y,a2.z,a2.w, bfh[2*nt], bfh[2*nt+1]);
                }
            }

            // refill A ring for the NEXT tile now; LDG latency hides behind epilogue
            af[0][0] = pNext[0];    af[0][1] = pNext[32];    af[0][2] = pNext[64];
            af[1][0] = pNext[96];   af[1][1] = pNext[96+32]; af[1][2] = pNext[96+64];

            // ---- epilogue: f16x2 gates + h update on (b, b+1) pairs ----
            const unsigned short* CH = (const unsigned short*)(sm + cur);
            unsigned short* NH = (unsigned short*)(sm + nxt);
            const int jA = 16*g + gr;
            #pragma unroll
            for (int rp = 0; rp < 2; rp++) {
                const int j = jA + 8*rp;
                const __half2 brh = __float2half2_rn(0.5f*bsr[j]);
                const __half2 bzh = __float2half2_rn(0.5f*bsz[j]);
                const __half2 bhh = __float2half2_rn(bhn[j]);
                const __half2 bih = __float2half2_rn(bin[j]);
                #pragma unroll
                for (int nt = 0; nt < 4; nt++) {
                    const int b0 = nt*8 + 2*tig;
                    __half2 ar2 = __floats2half2_rn(acc[0][nt][2*rp], acc[0][nt][2*rp+1]);
                    __half2 az2 = __floats2half2_rn(acc[1][nt][2*rp], acc[1][nt][2*rp+1]);
                    __half2 an2 = __floats2half2_rn(acc[2][nt][2*rp], acc[2][nt][2*rp+1]);
                    // sigmoid(x) = 0.5*tanh(0.5x)+0.5, pair-packed, biases in f16
                    __half2 rr2 = __hfma2(tanh2(__hfma2(ar2, h05, brh)), h05, h05);
                    __half2 zz2 = __hfma2(tanh2(__hfma2(az2, h05, bzh)), h05, h05);
                    __half2 nn2 = tanh2(__hfma2(rr2, __hadd2(an2, bhh), bih));
                    // hold pair
                    uint32_t hw = (uint32_t)CH[b0*HP + j] | ((uint32_t)CH[(b0+1)*HP + j] << 16);
                    __half2 hold2 = *reinterpret_cast<__half2*>(&hw);
                    __half2 hnew2 = __hfma2(zz2, __hsub2(hold2, nn2), nn2);
                    uint32_t hv = *reinterpret_cast<uint32_t*>(&hnew2);
                    NH[b0*HP + j]     = (unsigned short)(hv & 0xffffu);
                    NH[(b0+1)*HP + j] = (unsigned short)(hv >> 16);
                }
            }
        }

        __syncthreads();   // h_next complete, visible to all

        // ---- output projection into SMEM ring: out[b,t,:] = h_new @ ow^T + ob ----
        if (tid < 2*MROWS) {
            const int m = tid >> 1, o = tid & 1;
            float s = ob[o];
            const uint4* hh = (const uint4*)(sm + nxt + (size_t)m*HROW);
            const float* wp = ow + o*256;
            #pragma unroll 8
            for (int i = 0; i < 32; i++) {
                uint4 Hv = hh[i];
                const __half2 h2[4] = {
                    *(const __half2*)&Hv.x, *(const __half2*)&Hv.y,
                    *(const __half2*)&Hv.z, *(const __half2*)&Hv.w };
                const float* wq = wp + i*8;
                #pragma unroll
                for (int q = 0; q < 4; q++) {
                    float2 e = __half22float2(h2[q]);
                    s += e.x * wq[2*q] + e.y * wq[2*q + 1];
                }
            }
            obuf[(m*20 + (t % 20))*2 + o] = s;
        }

        // ---- coalesced flush every 20 steps (180 = 9*20) ----
        if ((t % 20) == 19) {
            __syncthreads();
            const int m = tid >> 3, q = tid & 7;   // 32 rows x 8 threads
            float* dst = out + (size_t)(mbase + m)*360 + (t - 19)*2 + q*5;
            const float* src = obuf + m*40 + q*5;
            #pragma unroll
            for (int i = 0; i < 5; i++) dst[i] = src[i];
        }

        uint32_t tmp = cur; cur = nxt; nxt = tmp;
    }
}

extern "C" void kernel_launch(void* const* d_in, const int* in_sizes, int n_in,
                              void* d_out, int out_size)
{
    (void)in_sizes; (void)n_in; (void)out_size;
    const float* z     = (const float*)d_in[0];
    const float* fc_w  = (const float*)d_in[1];
    const float* fc_b  = (const float*)d_in[2];
    /* d_in[3] = w_ih unused: GRU input is all-zeros, gi == b_ih */
    const float* b_ih  = (const float*)d_in[4];
    const float* w_hh  = (const float*)d_in[5];
    const float* b_hh  = (const float*)d_in[6];
    const float* out_w = (const float*)d_in[7];
    const float* out_b = (const float*)d_in[8];

    prep_w<<<96, 256>>>(w_hh);

    cudaFuncSetAttribute(gru_hmma_kernel,
                         cudaFuncAttributeMaxDynamicSharedMemorySize, SMEM_SZ);
    gru_hmma_kernel<<<NCTA, NTHR, SMEM_SZ>>>(
        z, fc_w, fc_b, b_ih, b_hh, out_w, out_b, (float*)d_out);
}